// round 7
// baseline (speedup 1.0000x reference)
#include <cuda_runtime.h>
#include <math.h>

#define BB 4
#define NN 16384
#define DD 64
#define HH 8
#define SPLITS 64
#define CT 64                 // tokens per tile/chunk (halved for 3 CTAs/SM)
#define XSS 68
#define L2_10K 0.4152410118609203f   // log2(10000)/32

typedef unsigned long long u64;

__device__ __forceinline__ u64 pk2(float a, float b) {
    u64 r;
    asm("mov.b64 %0, {%1, %2};" : "=l"(r)
        : "r"(__float_as_uint(a)), "r"(__float_as_uint(b)));
    return r;
}
__device__ __forceinline__ float2 up2(u64 a) {
    unsigned int lo, hi;
    asm("mov.b64 {%0, %1}, %2;" : "=r"(lo), "=r"(hi) : "l"(a));
    float2 r; r.x = __uint_as_float(lo); r.y = __uint_as_float(hi);
    return r;
}
__device__ __forceinline__ void fma2(u64& d, u64 a, u64 b) {
    asm("fma.rn.f32x2 %0, %1, %2, %0;" : "+l"(d) : "l"(a), "l"(b));
}
__device__ __forceinline__ u64 add2(u64 a, u64 b) {
    u64 r; asm("add.rn.f32x2 %0, %1, %2;" : "=l"(r) : "l"(a), "l"(b)); return r;
}
__device__ __forceinline__ u64 mul2(u64 a, u64 b) {
    u64 r; asm("mul.rn.f32x2 %0, %1, %2;" : "=l"(r) : "l"(a), "l"(b)); return r;
}

// scratch (static, no allocation)
__device__ float g_kv_part[BB * HH * SPLITS * DD * DD];   // 33.5 MB
__device__ float g_M[BB * HH * DD * DD];                  // 512 KB
__device__ float g_tabc[BB * NN * 32];                    // 8 MB
__device__ float g_tabs[BB * NN * 32];                    // 8 MB

// =====================================================================
// Kernel 0: RoPE cos/sin table
// =====================================================================
__global__ __launch_bounds__(256)
void tab_kernel(const float* __restrict__ pos)
{
    int idx = blockIdx.x * 256 + threadIdx.x;
    int fi = idx & 31;
    int bt = idx >> 5;
    float f = pos[bt] * 64.f * exp2f(-(float)fi * L2_10K);
    float s_, c_;
    sincosf(f, &s_, &c_);
    g_tabc[idx] = c_;
    g_tabs[idx] = s_;
}

// =====================================================================
// Kernel A: per (b,h,split): k/v proj (warp-specialized) + reg LN/RoPE
//           + kv = k^T v (register accumulators)
// smem: xs(=vs)[64][68] + ks[64][68] + wk[64][64] + wv[64][64] = 66 KB
// =====================================================================
__global__ __launch_bounds__(256, 3)
void kv_kernel(const float* __restrict__ x,
               const float* __restrict__ Wk, const float* __restrict__ Wv)
{
    extern __shared__ float sm[];
    float* xs = sm;                     // [64][68], becomes vs
    float* ks = sm + CT * XSS;          // [64][68]
    float* wk = sm + 2 * CT * XSS;      // [64][64]
    float* wv = wk + 4096;              // [64][64]

    const int tid = threadIdx.x;
    const int b = blockIdx.z, h = blockIdx.y, s = blockIdx.x;

    #pragma unroll
    for (int r = 0; r < 16; r++) {
        int idx = tid + r * 256;
        int i = idx >> 6, o = idx & 63;
        wk[idx] = Wk[i * 512 + h * 64 + o];
        wv[idx] = Wv[i * 512 + h * 64 + o];
    }

    const bool kwarp = (tid < 128);
    const int local = tid & 127;
    const int lane  = local & 31;
    const int wl    = local >> 5;        // 0..3
    const int og    = lane >> 2;         // 0..7 (HIGH bits -> conflict-free LDS.128)
    const int tl    = lane & 3;
    const int tg    = wl * 4 + tl;       // 0..15 token group
    const int o0    = og * 8;
    const float* W  = kwarp ? wk : wv;
    float* dstbuf   = kwarp ? ks : xs;   // vs aliases xs
    const float sgn = (og < 4) ? -1.f : 1.f;
    const u64 sgn2  = pk2(sgn, sgn);
    const int fbase = o0 & 31;

    // kv accumulator tile: 2 d-rows x 8 e-cols per thread
    const int lane8 = tid & 31;
    const int eg = lane8 >> 2;                       // 0..7
    const int dg = (tid >> 5) * 4 + (lane8 & 3);     // 0..31
    const int d0 = dg * 2;
    const int e0 = eg * 8;
    u64 kva[2][4];
    #pragma unroll
    for (int dj = 0; dj < 2; dj++)
        #pragma unroll
        for (int p = 0; p < 4; p++) kva[dj][p] = 0ull;

    __syncthreads();

    const int tok_per_blk = NN / SPLITS;            // 256
    #pragma unroll 1
    for (int c = 0; c < tok_per_blk / CT; c++) {    // 4 chunks of 64 tokens
        const int tbase = s * tok_per_blk + c * CT;
        const float* xg = x + ((size_t)b * NN + tbase) * 64;

        __syncthreads();    // previous chunk's vs readers done
        #pragma unroll
        for (int r = 0; r < 16; r++) {
            int idx = tid + r * 256;
            xs[(idx >> 6) * XSS + (idx & 63)] = xg[idx];
        }
        __syncthreads();

        // ---- projection: 4 tokens (t = tg+16j) x 8 outputs, i-pair loads ----
        u64 acc[4][4];
        #pragma unroll
        for (int j = 0; j < 4; j++)
            #pragma unroll
            for (int p = 0; p < 4; p++) acc[j][p] = 0ull;

        #pragma unroll 2
        for (int i2 = 0; i2 < 32; i2++) {
            const int i = 2 * i2;
            ulonglong2 wa0 = *(const ulonglong2*)&W[i * 64 + o0];
            ulonglong2 wa1 = *(const ulonglong2*)&W[i * 64 + o0 + 4];
            ulonglong2 wb0 = *(const ulonglong2*)&W[(i + 1) * 64 + o0];
            ulonglong2 wb1 = *(const ulonglong2*)&W[(i + 1) * 64 + o0 + 4];
            u64 w0[4] = { wa0.x, wa0.y, wa1.x, wa1.y };
            u64 w1[4] = { wb0.x, wb0.y, wb1.x, wb1.y };
            #pragma unroll
            for (int j = 0; j < 4; j++) {
                u64 xp = *(const u64*)&xs[(tg + 16 * j) * XSS + i];
                float2 xf = up2(xp);
                u64 xl = pk2(xf.x, xf.x);
                u64 xh = pk2(xf.y, xf.y);
                #pragma unroll
                for (int p = 0; p < 4; p++) {
                    fma2(acc[j][p], xl, w0[p]);
                    fma2(acc[j][p], xh, w1[p]);
                }
            }
        }
        __syncthreads();    // xs reads done (v-warps will overwrite it)

        // ---- LN in registers (8-lane groups via xor 4/8/16) + RoPE for k ----
        #pragma unroll
        for (int j = 0; j < 4; j++) {
            const int t = tg + 16 * j;
            u64 t01 = add2(acc[j][0], acc[j][1]);
            u64 t23 = add2(acc[j][2], acc[j][3]);
            float2 sf = up2(add2(t01, t23));
            float s1 = sf.x + sf.y;
            u64 q01 = add2(mul2(acc[j][0], acc[j][0]), mul2(acc[j][1], acc[j][1]));
            u64 q23 = add2(mul2(acc[j][2], acc[j][2]), mul2(acc[j][3], acc[j][3]));
            float2 qf = up2(add2(q01, q23));
            float s2 = qf.x + qf.y;
            #pragma unroll
            for (int m = 4; m <= 16; m <<= 1) {
                s1 += __shfl_xor_sync(0xffffffffu, s1, m);
                s2 += __shfl_xor_sync(0xffffffffu, s2, m);
            }
            float mean = s1 * (1.f / 64.f);
            float var  = fmaxf(s2 * (1.f / 64.f) - mean * mean, 0.f);
            float rs   = rsqrtf(var + 1e-5f);
            float mr   = -mean * rs;
            u64 rs2 = pk2(rs, rs), mr2 = pk2(mr, mr);
            u64 kn[4];
            #pragma unroll
            for (int p = 0; p < 4; p++) { kn[p] = mr2; fma2(kn[p], acc[j][p], rs2); }

            if (kwarp) {   // RoPE; partner og^4 == lane^16
                u64 pn[4];
                #pragma unroll
                for (int p = 0; p < 4; p++)
                    pn[p] = __shfl_xor_sync(0xffffffffu, kn[p], 16);
                const float* tc = &g_tabc[((size_t)(b * NN + tbase + t)) * 32 + fbase];
                const float* ts = &g_tabs[((size_t)(b * NN + tbase + t)) * 32 + fbase];
                float4 c0 = *(const float4*)tc;
                float4 c1 = *(const float4*)(tc + 4);
                float4 s0 = *(const float4*)ts;
                float4 s1v = *(const float4*)(ts + 4);
                u64 cc[4] = { pk2(c0.x, c0.y), pk2(c0.z, c0.w),
                              pk2(c1.x, c1.y), pk2(c1.z, c1.w) };
                u64 ss[4] = { pk2(s0.x, s0.y), pk2(s0.z, s0.w),
                              pk2(s1v.x, s1v.y), pk2(s1v.z, s1v.w) };
                #pragma unroll
                for (int p = 0; p < 4; p++) {
                    u64 r = mul2(kn[p], cc[p]);
                    fma2(r, pn[p], mul2(ss[p], sgn2));
                    kn[p] = r;
                }
            }
            #pragma unroll
            for (int sr = 0; sr < 4; sr++) {       // rotated store order
                int p = (sr + og) & 3;
                *(u64*)&dstbuf[t * XSS + o0 + 2 * p] = kn[p];
            }
        }
        __syncthreads();

        // ---- kv[d][e] += sum_t k[t][d]*v[t][e] ----
        #pragma unroll 8
        for (int t = 0; t < CT; t++) {
            u64 kp = *(const u64*)&ks[t * XSS + d0];
            float2 kf = up2(kp);
            u64 kk0 = pk2(kf.x, kf.x), kk1 = pk2(kf.y, kf.y);
            ulonglong2 v0 = *(const ulonglong2*)&xs[t * XSS + e0];
            ulonglong2 v1 = *(const ulonglong2*)&xs[t * XSS + e0 + 4];
            u64 vp[4] = { v0.x, v0.y, v1.x, v1.y };
            #pragma unroll
            for (int p = 0; p < 4; p++) {
                fma2(kva[0][p], kk0, vp[p]);
                fma2(kva[1][p], kk1, vp[p]);
            }
        }
    }

    float* dst = g_kv_part + ((size_t)((b * HH + h) * SPLITS + s)) * 4096;
    #pragma unroll
    for (int dj = 0; dj < 2; dj++)
        #pragma unroll
        for (int p = 0; p < 4; p++)
            *(u64*)&dst[(d0 + dj) * 64 + e0 + 2 * p] = kva[dj][p];
}

// =====================================================================
// Kernel B: reduce splits, M_h = (kv_h @ Wo_h) / N
// =====================================================================
__global__ __launch_bounds__(256, 1)
void m_kernel(const float* __restrict__ Wo)
{
    __shared__ float kvs[64 * 66];
    __shared__ float wo[64 * 64];
    const int tid = threadIdx.x;
    const int h = blockIdx.x, b = blockIdx.y;
    const float* src = g_kv_part + (size_t)(b * HH + h) * SPLITS * 4096;

    #pragma unroll
    for (int r = 0; r < 16; r++) {
        int idx = tid + r * 256;
        float acc = 0.f;
        #pragma unroll 4
        for (int s = 0; s < SPLITS; s++) acc += src[s * 4096 + idx];
        int i = idx >> 6, j = idx & 63;
        kvs[i * 66 + j] = acc;
        wo[idx] = Wo[(h * 64 + i) * 64 + j];
    }
    __syncthreads();

    const int i0 = (tid >> 3) * 2;
    const int d0 = (tid & 7) * 8;
    u64 a[2][4];
    #pragma unroll
    for (int ij = 0; ij < 2; ij++)
        #pragma unroll
        for (int p = 0; p < 4; p++) a[ij][p] = 0ull;

    #pragma unroll 8
    for (int j = 0; j < 64; j++) {
        float k0 = kvs[i0 * 66 + j], k1 = kvs[(i0 + 1) * 66 + j];
        u64 p0 = pk2(k0, k0), p1 = pk2(k1, k1);
        ulonglong2 w0 = *(const ulonglong2*)&wo[j * 64 + d0];
        ulonglong2 w1 = *(const ulonglong2*)&wo[j * 64 + d0 + 4];
        u64 wp[4] = { w0.x, w0.y, w1.x, w1.y };
        #pragma unroll
        for (int p = 0; p < 4; p++) {
            fma2(a[0][p], p0, wp[p]);
            fma2(a[1][p], p1, wp[p]);
        }
    }
    const float sc = 1.f / (float)NN;
    const u64 sc2 = pk2(sc, sc);
    float* dst = g_M + ((size_t)(b * 512 + h * 64)) * 64;
    #pragma unroll
    for (int ij = 0; ij < 2; ij++)
        #pragma unroll
        for (int p = 0; p < 4; p++)
            *(u64*)&dst[(i0 + ij) * 64 + d0 + 2 * p] = mul2(a[ij][p], sc2);
}

// =====================================================================
// Kernel C: out = sum_h RoPE(x @ Wq_h) @ M_h   (64-token tiles)
// smem: xs[64][68] + qs[64][68] + wq[64][64] + mm[64][64] = 66 KB
// =====================================================================
__global__ __launch_bounds__(256, 3)
void out_kernel(const float* __restrict__ x,
                const float* __restrict__ Wq, float* __restrict__ out)
{
    extern __shared__ float sm[];
    float* xs = sm;
    float* qs = sm + CT * XSS;
    float* wq = sm + 2 * CT * XSS;
    float* mm = wq + 4096;

    const int tid = threadIdx.x;
    const int b = blockIdx.y;
    const int tbase = blockIdx.x * CT;
    const float* xg = x + ((size_t)b * NN + tbase) * 64;

    #pragma unroll
    for (int r = 0; r < 16; r++) {
        int idx = tid + r * 256;
        xs[(idx >> 6) * XSS + (idx & 63)] = xg[idx];
    }

    const int lane = tid & 31;
    const int w8   = tid >> 5;          // 0..7
    const int og   = lane >> 2;         // 0..7 (high lane bits)
    const int tl   = lane & 3;
    const int tg   = w8 * 4 + tl;       // 0..31 token group
    const int o0   = og * 8;
    const float sgn = (og < 4) ? -1.f : 1.f;
    const u64 sgn2 = pk2(sgn, sgn);
    const int fbase = o0 & 31;

    u64 oa[2][4];
    #pragma unroll
    for (int j = 0; j < 2; j++)
        #pragma unroll
        for (int p = 0; p < 4; p++) oa[j][p] = 0ull;

    __syncthreads();

    #pragma unroll 1
    for (int h = 0; h < HH; h++) {
        #pragma unroll
        for (int r = 0; r < 16; r++) {
            int idx = tid + r * 256;
            int i = idx >> 6, o = idx & 63;
            wq[idx] = Wq[i * 512 + h * 64 + o];
            mm[idx] = g_M[(size_t)(b * 512 + h * 64 + i) * 64 + o];
        }
        __syncthreads();

        // q = x @ Wq_h : 2 tokens (t = tg+32j) x 8 outputs, i-pair loads
        u64 aq[2][4];
        #pragma unroll
        for (int j = 0; j < 2; j++)
            #pragma unroll
            for (int p = 0; p < 4; p++) aq[j][p] = 0ull;

        #pragma unroll 2
        for (int i2 = 0; i2 < 32; i2++) {
            const int i = 2 * i2;
            ulonglong2 wa0 = *(const ulonglong2*)&wq[i * 64 + o0];
            ulonglong2 wa1 = *(const ulonglong2*)&wq[i * 64 + o0 + 4];
            ulonglong2 wb0 = *(const ulonglong2*)&wq[(i + 1) * 64 + o0];
            ulonglong2 wb1 = *(const ulonglong2*)&wq[(i + 1) * 64 + o0 + 4];
            u64 w0[4] = { wa0.x, wa0.y, wa1.x, wa1.y };
            u64 w1[4] = { wb0.x, wb0.y, wb1.x, wb1.y };
            #pragma unroll
            for (int j = 0; j < 2; j++) {
                u64 xp = *(const u64*)&xs[(tg + 32 * j) * XSS + i];
                float2 xf = up2(xp);
                u64 xl = pk2(xf.x, xf.x);
                u64 xh = pk2(xf.y, xf.y);
                #pragma unroll
                for (int p = 0; p < 4; p++) {
                    fma2(aq[j][p], xl, w0[p]);
                    fma2(aq[j][p], xh, w1[p]);
                }
            }
        }

        // RoPE(q) in registers, single store to qs
        #pragma unroll
        for (int j = 0; j < 2; j++) {
            const int t = tg + 32 * j;
            u64 pn[4];
            #pragma unroll
            for (int p = 0; p < 4; p++)
                pn[p] = __shfl_xor_sync(0xffffffffu, aq[j][p], 16);
            const float* tc = &g_tabc[((size_t)(b * NN + tbase + t)) * 32 + fbase];
            const float* ts = &g_tabs[((size_t)(b * NN + tbase + t)) * 32 + fbase];
            float4 c0 = *(const float4*)tc;
            float4 c1 = *(const float4*)(tc + 4);
            float4 s0 = *(const float4*)ts;
            float4 s1v = *(const float4*)(ts + 4);
            u64 cc[4] = { pk2(c0.x, c0.y), pk2(c0.z, c0.w),
                          pk2(c1.x, c1.y), pk2(c1.z, c1.w) };
            u64 ss[4] = { pk2(s0.x, s0.y), pk2(s0.z, s0.w),
                          pk2(s1v.x, s1v.y), pk2(s1v.z, s1v.w) };
            #pragma unroll
            for (int sr = 0; sr < 4; sr++) {
                int p = (sr + og) & 3;
                u64 r = mul2(aq[j][p], cc[p]);
                fma2(r, pn[p], mul2(ss[p], sgn2));
                *(u64*)&qs[t * XSS + o0 + 2 * p] = r;
            }
        }
        __syncthreads();

        // out += q_rope @ M_h  (i-pair loads from qs)
        #pragma unroll 2
        for (int i2 = 0; i2 < 32; i2++) {
            const int i = 2 * i2;
            ulonglong2 ma0 = *(const ulonglong2*)&mm[i * 64 + o0];
            ulonglong2 ma1 = *(const ulonglong2*)&mm[i * 64 + o0 + 4];
            ulonglong2 mb0 = *(const ulonglong2*)&mm[(i + 1) * 64 + o0];
            ulonglong2 mb1 = *(const ulonglong2*)&mm[(i + 1) * 64 + o0 + 4];
            u64 m0[4] = { ma0.x, ma0.y, ma1.x, ma1.y };
            u64 m1[4] = { mb0.x, mb0.y, mb1.x, mb1.y };
            #pragma unroll
            for (int j = 0; j < 2; j++) {
                u64 qp = *(const u64*)&qs[(tg + 32 * j) * XSS + i];
                float2 qf = up2(qp);
                u64 ql = pk2(qf.x, qf.x);
                u64 qh = pk2(qf.y, qf.y);
                #pragma unroll
                for (int p = 0; p < 4; p++) {
                    fma2(oa[j][p], ql, m0[p]);
                    fma2(oa[j][p], qh, m1[p]);
                }
            }
        }
        __syncthreads();
    }

    float* outg = out + ((size_t)b * NN + tbase) * 64;
    #pragma unroll
    for (int j = 0; j < 2; j++)
        #pragma unroll
        for (int p = 0; p < 4; p++)
            *(u64*)&outg[(tg + 32 * j) * 64 + o0 + 2 * p] = oa[j][p];
}

// =====================================================================
extern "C" void kernel_launch(void* const* d_in, const int* in_sizes, int n_in,
                              void* d_out, int out_size)
{
    const float* x   = (const float*)d_in[0];
    const float* pos = (const float*)d_in[1];
    const float* Wq  = (const float*)d_in[2];
    const float* Wk  = (const float*)d_in[3];
    const float* Wv  = (const float*)d_in[4];
    const float* Wo  = (const float*)d_in[5];
    float* out = (float*)d_out;

    const int SMEM_T = (2 * CT * XSS + 2 * 4096) * 4;   // 67584 B = 66 KB
    cudaFuncSetAttribute(kv_kernel,  cudaFuncAttributeMaxDynamicSharedMemorySize, SMEM_T);
    cudaFuncSetAttribute(out_kernel, cudaFuncAttributeMaxDynamicSharedMemorySize, SMEM_T);

    tab_kernel<<<BB * NN * 32 / 256, 256>>>(pos);
    kv_kernel<<<dim3(SPLITS, HH, BB), 256, SMEM_T>>>(x, Wk, Wv);
    m_kernel<<<dim3(HH, BB), 256>>>(Wo);
    out_kernel<<<dim3(NN / CT, BB), 256, SMEM_T>>>(x, Wq, out);
}

// round 8
// speedup vs baseline: 1.0100x; 1.0100x over previous
#include <cuda_runtime.h>
#include <math.h>

#define BB 4
#define NN 16384
#define DD 64
#define HH 8
#define SPLITS 64
#define CT 64                 // tokens per tile/chunk (halved for 3 CTAs/SM)
#define XSS 68
#define L2_10K 0.4152410118609203f   // log2(10000)/32

typedef unsigned long long u64;

__device__ __forceinline__ u64 pk2(float a, float b) {
    u64 r;
    asm("mov.b64 %0, {%1, %2};" : "=l"(r)
        : "r"(__float_as_uint(a)), "r"(__float_as_uint(b)));
    return r;
}
__device__ __forceinline__ float2 up2(u64 a) {
    unsigned int lo, hi;
    asm("mov.b64 {%0, %1}, %2;" : "=r"(lo), "=r"(hi) : "l"(a));
    float2 r; r.x = __uint_as_float(lo); r.y = __uint_as_float(hi);
    return r;
}
__device__ __forceinline__ void fma2(u64& d, u64 a, u64 b) {
    asm("fma.rn.f32x2 %0, %1, %2, %0;" : "+l"(d) : "l"(a), "l"(b));
}
__device__ __forceinline__ u64 add2(u64 a, u64 b) {
    u64 r; asm("add.rn.f32x2 %0, %1, %2;" : "=l"(r) : "l"(a), "l"(b)); return r;
}
__device__ __forceinline__ u64 mul2(u64 a, u64 b) {
    u64 r; asm("mul.rn.f32x2 %0, %1, %2;" : "=l"(r) : "l"(a), "l"(b)); return r;
}

// scratch (static, no allocation)
__device__ float g_kv_part[BB * HH * SPLITS * DD * DD];   // 33.5 MB
__device__ float g_M[BB * HH * DD * DD];                  // 512 KB
__device__ float g_tabc[BB * NN * 32];                    // 8 MB
__device__ float g_tabs[BB * NN * 32];                    // 8 MB

// =====================================================================
// Kernel 0: RoPE cos/sin table
// =====================================================================
__global__ __launch_bounds__(256)
void tab_kernel(const float* __restrict__ pos)
{
    int idx = blockIdx.x * 256 + threadIdx.x;
    int fi = idx & 31;
    int bt = idx >> 5;
    float f = pos[bt] * 64.f * exp2f(-(float)fi * L2_10K);
    float s_, c_;
    sincosf(f, &s_, &c_);
    g_tabc[idx] = c_;
    g_tabs[idx] = s_;
}

// =====================================================================
// Kernel A: per (b,h,split): k/v proj (warp-specialized) + reg LN/RoPE
//           + kv = k^T v (register accumulators)
// smem: xs(=vs)[64][68] + ks[64][68] + wk[64][64] + wv[64][64] = 66 KB
// =====================================================================
__global__ __launch_bounds__(256, 3)
void kv_kernel(const float* __restrict__ x,
               const float* __restrict__ Wk, const float* __restrict__ Wv)
{
    extern __shared__ float sm[];
    float* xs = sm;                     // [64][68], becomes vs
    float* ks = sm + CT * XSS;          // [64][68]
    float* wk = sm + 2 * CT * XSS;      // [64][64]
    float* wv = wk + 4096;              // [64][64]

    const int tid = threadIdx.x;
    const int b = blockIdx.z, h = blockIdx.y, s = blockIdx.x;

    #pragma unroll
    for (int r = 0; r < 16; r++) {
        int idx = tid + r * 256;
        int i = idx >> 6, o = idx & 63;
        wk[idx] = Wk[i * 512 + h * 64 + o];
        wv[idx] = Wv[i * 512 + h * 64 + o];
    }

    const bool kwarp = (tid < 128);
    const int local = tid & 127;
    const int lane  = local & 31;
    const int wl    = local >> 5;        // 0..3
    const int og    = lane >> 2;         // 0..7 (HIGH bits -> conflict-free LDS.128)
    const int tl    = lane & 3;
    const int tg    = wl * 4 + tl;       // 0..15 token group
    const int o0    = og * 8;
    const float* W  = kwarp ? wk : wv;
    float* dstbuf   = kwarp ? ks : xs;   // vs aliases xs
    const float sgn = (og < 4) ? -1.f : 1.f;
    const u64 sgn2  = pk2(sgn, sgn);
    const int fbase = o0 & 31;

    // kv accumulator tile: 2 d-rows x 8 e-cols per thread
    const int lane8 = tid & 31;
    const int eg = lane8 >> 2;                       // 0..7
    const int dg = (tid >> 5) * 4 + (lane8 & 3);     // 0..31
    const int d0 = dg * 2;
    const int e0 = eg * 8;
    u64 kva[2][4];
    #pragma unroll
    for (int dj = 0; dj < 2; dj++)
        #pragma unroll
        for (int p = 0; p < 4; p++) kva[dj][p] = 0ull;

    __syncthreads();

    const int tok_per_blk = NN / SPLITS;            // 256
    #pragma unroll 1
    for (int c = 0; c < tok_per_blk / CT; c++) {    // 4 chunks of 64 tokens
        const int tbase = s * tok_per_blk + c * CT;
        const float* xg = x + ((size_t)b * NN + tbase) * 64;

        __syncthreads();    // previous chunk's vs readers done
        #pragma unroll
        for (int r = 0; r < 16; r++) {
            int idx = tid + r * 256;
            xs[(idx >> 6) * XSS + (idx & 63)] = xg[idx];
        }
        __syncthreads();

        // ---- projection: 4 tokens (t = tg+16j) x 8 outputs, i-pair loads ----
        u64 acc[4][4];
        #pragma unroll
        for (int j = 0; j < 4; j++)
            #pragma unroll
            for (int p = 0; p < 4; p++) acc[j][p] = 0ull;

        #pragma unroll 2
        for (int i2 = 0; i2 < 32; i2++) {
            const int i = 2 * i2;
            ulonglong2 wa0 = *(const ulonglong2*)&W[i * 64 + o0];
            ulonglong2 wa1 = *(const ulonglong2*)&W[i * 64 + o0 + 4];
            ulonglong2 wb0 = *(const ulonglong2*)&W[(i + 1) * 64 + o0];
            ulonglong2 wb1 = *(const ulonglong2*)&W[(i + 1) * 64 + o0 + 4];
            u64 w0[4] = { wa0.x, wa0.y, wa1.x, wa1.y };
            u64 w1[4] = { wb0.x, wb0.y, wb1.x, wb1.y };
            #pragma unroll
            for (int j = 0; j < 4; j++) {
                u64 xp = *(const u64*)&xs[(tg + 16 * j) * XSS + i];
                float2 xf = up2(xp);
                u64 xl = pk2(xf.x, xf.x);
                u64 xh = pk2(xf.y, xf.y);
                #pragma unroll
                for (int p = 0; p < 4; p++) {
                    fma2(acc[j][p], xl, w0[p]);
                    fma2(acc[j][p], xh, w1[p]);
                }
            }
        }
        __syncthreads();    // xs reads done (v-warps will overwrite it)

        // ---- LN in registers (8-lane groups via xor 4/8/16) + RoPE for k ----
        #pragma unroll
        for (int j = 0; j < 4; j++) {
            const int t = tg + 16 * j;
            u64 t01 = add2(acc[j][0], acc[j][1]);
            u64 t23 = add2(acc[j][2], acc[j][3]);
            float2 sf = up2(add2(t01, t23));
            float s1 = sf.x + sf.y;
            u64 q01 = add2(mul2(acc[j][0], acc[j][0]), mul2(acc[j][1], acc[j][1]));
            u64 q23 = add2(mul2(acc[j][2], acc[j][2]), mul2(acc[j][3], acc[j][3]));
            float2 qf = up2(add2(q01, q23));
            float s2 = qf.x + qf.y;
            #pragma unroll
            for (int m = 4; m <= 16; m <<= 1) {
                s1 += __shfl_xor_sync(0xffffffffu, s1, m);
                s2 += __shfl_xor_sync(0xffffffffu, s2, m);
            }
            float mean = s1 * (1.f / 64.f);
            float var  = fmaxf(s2 * (1.f / 64.f) - mean * mean, 0.f);
            float rs   = rsqrtf(var + 1e-5f);
            float mr   = -mean * rs;
            u64 rs2 = pk2(rs, rs), mr2 = pk2(mr, mr);
            u64 kn[4];
            #pragma unroll
            for (int p = 0; p < 4; p++) { kn[p] = mr2; fma2(kn[p], acc[j][p], rs2); }

            if (kwarp) {   // RoPE; partner og^4 == lane^16
                u64 pn[4];
                #pragma unroll
                for (int p = 0; p < 4; p++)
                    pn[p] = __shfl_xor_sync(0xffffffffu, kn[p], 16);
                const float* tc = &g_tabc[((size_t)(b * NN + tbase + t)) * 32 + fbase];
                const float* ts = &g_tabs[((size_t)(b * NN + tbase + t)) * 32 + fbase];
                float4 c0 = *(const float4*)tc;
                float4 c1 = *(const float4*)(tc + 4);
                float4 s0 = *(const float4*)ts;
                float4 s1v = *(const float4*)(ts + 4);
                u64 cc[4] = { pk2(c0.x, c0.y), pk2(c0.z, c0.w),
                              pk2(c1.x, c1.y), pk2(c1.z, c1.w) };
                u64 ss[4] = { pk2(s0.x, s0.y), pk2(s0.z, s0.w),
                              pk2(s1v.x, s1v.y), pk2(s1v.z, s1v.w) };
                #pragma unroll
                for (int p = 0; p < 4; p++) {
                    u64 r = mul2(kn[p], cc[p]);
                    fma2(r, pn[p], mul2(ss[p], sgn2));
                    kn[p] = r;
                }
            }
            #pragma unroll
            for (int sr = 0; sr < 4; sr++) {       // rotated store order
                int p = (sr + og) & 3;
                *(u64*)&dstbuf[t * XSS + o0 + 2 * p] = kn[p];
            }
        }
        __syncthreads();

        // ---- kv[d][e] += sum_t k[t][d]*v[t][e] ----
        #pragma unroll 8
        for (int t = 0; t < CT; t++) {
            u64 kp = *(const u64*)&ks[t * XSS + d0];
            float2 kf = up2(kp);
            u64 kk0 = pk2(kf.x, kf.x), kk1 = pk2(kf.y, kf.y);
            ulonglong2 v0 = *(const ulonglong2*)&xs[t * XSS + e0];
            ulonglong2 v1 = *(const ulonglong2*)&xs[t * XSS + e0 + 4];
            u64 vp[4] = { v0.x, v0.y, v1.x, v1.y };
            #pragma unroll
            for (int p = 0; p < 4; p++) {
                fma2(kva[0][p], kk0, vp[p]);
                fma2(kva[1][p], kk1, vp[p]);
            }
        }
    }

    float* dst = g_kv_part + ((size_t)((b * HH + h) * SPLITS + s)) * 4096;
    #pragma unroll
    for (int dj = 0; dj < 2; dj++)
        #pragma unroll
        for (int p = 0; p < 4; p++)
            *(u64*)&dst[(d0 + dj) * 64 + e0 + 2 * p] = kva[dj][p];
}

// =====================================================================
// Kernel B: reduce splits, M_h = (kv_h @ Wo_h) / N
// =====================================================================
__global__ __launch_bounds__(256, 1)
void m_kernel(const float* __restrict__ Wo)
{
    __shared__ float kvs[64 * 66];
    __shared__ float wo[64 * 64];
    const int tid = threadIdx.x;
    const int h = blockIdx.x, b = blockIdx.y;
    const float* src = g_kv_part + (size_t)(b * HH + h) * SPLITS * 4096;

    #pragma unroll
    for (int r = 0; r < 16; r++) {
        int idx = tid + r * 256;
        float acc = 0.f;
        #pragma unroll 4
        for (int s = 0; s < SPLITS; s++) acc += src[s * 4096 + idx];
        int i = idx >> 6, j = idx & 63;
        kvs[i * 66 + j] = acc;
        wo[idx] = Wo[(h * 64 + i) * 64 + j];
    }
    __syncthreads();

    const int i0 = (tid >> 3) * 2;
    const int d0 = (tid & 7) * 8;
    u64 a[2][4];
    #pragma unroll
    for (int ij = 0; ij < 2; ij++)
        #pragma unroll
        for (int p = 0; p < 4; p++) a[ij][p] = 0ull;

    #pragma unroll 8
    for (int j = 0; j < 64; j++) {
        float k0 = kvs[i0 * 66 + j], k1 = kvs[(i0 + 1) * 66 + j];
        u64 p0 = pk2(k0, k0), p1 = pk2(k1, k1);
        ulonglong2 w0 = *(const ulonglong2*)&wo[j * 64 + d0];
        ulonglong2 w1 = *(const ulonglong2*)&wo[j * 64 + d0 + 4];
        u64 wp[4] = { w0.x, w0.y, w1.x, w1.y };
        #pragma unroll
        for (int p = 0; p < 4; p++) {
            fma2(a[0][p], p0, wp[p]);
            fma2(a[1][p], p1, wp[p]);
        }
    }
    const float sc = 1.f / (float)NN;
    const u64 sc2 = pk2(sc, sc);
    float* dst = g_M + ((size_t)(b * 512 + h * 64)) * 64;
    #pragma unroll
    for (int ij = 0; ij < 2; ij++)
        #pragma unroll
        for (int p = 0; p < 4; p++)
            *(u64*)&dst[(i0 + ij) * 64 + d0 + 2 * p] = mul2(a[ij][p], sc2);
}

// =====================================================================
// Kernel C: out = sum_h RoPE(x @ Wq_h) @ M_h   (64-token tiles)
// smem: xs[64][68] + qs[64][68] + wq[64][64] + mm[64][64] = 66 KB
// =====================================================================
__global__ __launch_bounds__(256, 3)
void out_kernel(const float* __restrict__ x,
                const float* __restrict__ Wq, float* __restrict__ out)
{
    extern __shared__ float sm[];
    float* xs = sm;
    float* qs = sm + CT * XSS;
    float* wq = sm + 2 * CT * XSS;
    float* mm = wq + 4096;

    const int tid = threadIdx.x;
    const int b = blockIdx.y;
    const int tbase = blockIdx.x * CT;
    const float* xg = x + ((size_t)b * NN + tbase) * 64;

    #pragma unroll
    for (int r = 0; r < 16; r++) {
        int idx = tid + r * 256;
        xs[(idx >> 6) * XSS + (idx & 63)] = xg[idx];
    }

    const int lane = tid & 31;
    const int w8   = tid >> 5;          // 0..7
    const int og   = lane >> 2;         // 0..7 (high lane bits)
    const int tl   = lane & 3;
    const int tg   = w8 * 4 + tl;       // 0..31 token group
    const int o0   = og * 8;
    const float sgn = (og < 4) ? -1.f : 1.f;
    const u64 sgn2 = pk2(sgn, sgn);
    const int fbase = o0 & 31;

    u64 oa[2][4];
    #pragma unroll
    for (int j = 0; j < 2; j++)
        #pragma unroll
        for (int p = 0; p < 4; p++) oa[j][p] = 0ull;

    __syncthreads();

    #pragma unroll 1
    for (int h = 0; h < HH; h++) {
        #pragma unroll
        for (int r = 0; r < 16; r++) {
            int idx = tid + r * 256;
            int i = idx >> 6, o = idx & 63;
            wq[idx] = Wq[i * 512 + h * 64 + o];
            mm[idx] = g_M[(size_t)(b * 512 + h * 64 + i) * 64 + o];
        }
        __syncthreads();

        // q = x @ Wq_h : 2 tokens (t = tg+32j) x 8 outputs, i-pair loads
        u64 aq[2][4];
        #pragma unroll
        for (int j = 0; j < 2; j++)
            #pragma unroll
            for (int p = 0; p < 4; p++) aq[j][p] = 0ull;

        #pragma unroll 2
        for (int i2 = 0; i2 < 32; i2++) {
            const int i = 2 * i2;
            ulonglong2 wa0 = *(const ulonglong2*)&wq[i * 64 + o0];
            ulonglong2 wa1 = *(const ulonglong2*)&wq[i * 64 + o0 + 4];
            ulonglong2 wb0 = *(const ulonglong2*)&wq[(i + 1) * 64 + o0];
            ulonglong2 wb1 = *(const ulonglong2*)&wq[(i + 1) * 64 + o0 + 4];
            u64 w0[4] = { wa0.x, wa0.y, wa1.x, wa1.y };
            u64 w1[4] = { wb0.x, wb0.y, wb1.x, wb1.y };
            #pragma unroll
            for (int j = 0; j < 2; j++) {
                u64 xp = *(const u64*)&xs[(tg + 32 * j) * XSS + i];
                float2 xf = up2(xp);
                u64 xl = pk2(xf.x, xf.x);
                u64 xh = pk2(xf.y, xf.y);
                #pragma unroll
                for (int p = 0; p < 4; p++) {
                    fma2(aq[j][p], xl, w0[p]);
                    fma2(aq[j][p], xh, w1[p]);
                }
            }
        }

        // RoPE(q) in registers, single store to qs
        #pragma unroll
        for (int j = 0; j < 2; j++) {
            const int t = tg + 32 * j;
            u64 pn[4];
            #pragma unroll
            for (int p = 0; p < 4; p++)
                pn[p] = __shfl_xor_sync(0xffffffffu, aq[j][p], 16);
            const float* tc = &g_tabc[((size_t)(b * NN + tbase + t)) * 32 + fbase];
            const float* ts = &g_tabs[((size_t)(b * NN + tbase + t)) * 32 + fbase];
            float4 c0 = *(const float4*)tc;
            float4 c1 = *(const float4*)(tc + 4);
            float4 s0 = *(const float4*)ts;
            float4 s1v = *(const float4*)(ts + 4);
            u64 cc[4] = { pk2(c0.x, c0.y), pk2(c0.z, c0.w),
                          pk2(c1.x, c1.y), pk2(c1.z, c1.w) };
            u64 ss[4] = { pk2(s0.x, s0.y), pk2(s0.z, s0.w),
                          pk2(s1v.x, s1v.y), pk2(s1v.z, s1v.w) };
            #pragma unroll
            for (int sr = 0; sr < 4; sr++) {
                int p = (sr + og) & 3;
                u64 r = mul2(aq[j][p], cc[p]);
                fma2(r, pn[p], mul2(ss[p], sgn2));
                *(u64*)&qs[t * XSS + o0 + 2 * p] = r;
            }
        }
        __syncthreads();

        // out += q_rope @ M_h  (i-pair loads from qs)
        #pragma unroll 2
        for (int i2 = 0; i2 < 32; i2++) {
            const int i = 2 * i2;
            ulonglong2 ma0 = *(const ulonglong2*)&mm[i * 64 + o0];
            ulonglong2 ma1 = *(const ulonglong2*)&mm[i * 64 + o0 + 4];
            ulonglong2 mb0 = *(const ulonglong2*)&mm[(i + 1) * 64 + o0];
            ulonglong2 mb1 = *(const ulonglong2*)&mm[(i + 1) * 64 + o0 + 4];
            u64 m0[4] = { ma0.x, ma0.y, ma1.x, ma1.y };
            u64 m1[4] = { mb0.x, mb0.y, mb1.x, mb1.y };
            #pragma unroll
            for (int j = 0; j < 2; j++) {
                u64 qp = *(const u64*)&qs[(tg + 32 * j) * XSS + i];
                float2 qf = up2(qp);
                u64 ql = pk2(qf.x, qf.x);
                u64 qh = pk2(qf.y, qf.y);
                #pragma unroll
                for (int p = 0; p < 4; p++) {
                    fma2(oa[j][p], ql, m0[p]);
                    fma2(oa[j][p], qh, m1[p]);
                }
            }
        }
        __syncthreads();
    }

    float* outg = out + ((size_t)b * NN + tbase) * 64;
    #pragma unroll
    for (int j = 0; j < 2; j++)
        #pragma unroll
        for (int p = 0; p < 4; p++)
            *(u64*)&outg[(tg + 32 * j) * 64 + o0 + 2 * p] = oa[j][p];
}

// =====================================================================
extern "C" void kernel_launch(void* const* d_in, const int* in_sizes, int n_in,
                              void* d_out, int out_size)
{
    const float* x   = (const float*)d_in[0];
    const float* pos = (const float*)d_in[1];
    const float* Wq  = (const float*)d_in[2];
    const float* Wk  = (const float*)d_in[3];
    const float* Wv  = (const float*)d_in[4];
    const float* Wo  = (const float*)d_in[5];
    float* out = (float*)d_out;

    const int SMEM_T = (2 * CT * XSS + 2 * 4096) * 4;   // 67584 B = 66 KB
    cudaFuncSetAttribute(kv_kernel,  cudaFuncAttributeMaxDynamicSharedMemorySize, SMEM_T);
    cudaFuncSetAttribute(out_kernel, cudaFuncAttributeMaxDynamicSharedMemorySize, SMEM_T);

    tab_kernel<<<BB * NN * 32 / 256, 256>>>(pos);
    kv_kernel<<<dim3(SPLITS, HH, BB), 256, SMEM_T>>>(x, Wk, Wv);
    m_kernel<<<dim3(HH, BB), 256>>>(Wo);
    out_kernel<<<dim3(NN / CT, BB), 256, SMEM_T>>>(x, Wq, out);
}

// round 9
// speedup vs baseline: 1.4330x; 1.4188x over previous
#include <cuda_runtime.h>
#include <math.h>

#define BB 4
#define NN 16384
#define HH 8
#define SPLITS 64
#define CT 64
#define OCT 128
#define XSS 68
#define L2_10K 0.4152410118609203f

typedef unsigned long long u64;
typedef unsigned int u32;

__device__ __forceinline__ u64 pk2(float a, float b) {
    u64 r;
    asm("mov.b64 %0, {%1, %2};" : "=l"(r)
        : "r"(__float_as_uint(a)), "r"(__float_as_uint(b)));
    return r;
}
__device__ __forceinline__ float2 up2(u64 a) {
    unsigned int lo, hi;
    asm("mov.b64 {%0, %1}, %2;" : "=r"(lo), "=r"(hi) : "l"(a));
    float2 r; r.x = __uint_as_float(lo); r.y = __uint_as_float(hi);
    return r;
}
__device__ __forceinline__ void fma2(u64& d, u64 a, u64 b) {
    asm("fma.rn.f32x2 %0, %1, %2, %0;" : "+l"(d) : "l"(a), "l"(b));
}
__device__ __forceinline__ u64 add2(u64 a, u64 b) {
    u64 r; asm("add.rn.f32x2 %0, %1, %2;" : "=l"(r) : "l"(a), "l"(b)); return r;
}
__device__ __forceinline__ u64 mul2(u64 a, u64 b) {
    u64 r; asm("mul.rn.f32x2 %0, %1, %2;" : "=l"(r) : "l"(a), "l"(b)); return r;
}

// bf16 helpers
__device__ __forceinline__ u32 cvt2(float hi, float lo) {
    u32 d; asm("cvt.rn.bf16x2.f32 %0, %1, %2;" : "=r"(d) : "f"(hi), "f"(lo));
    return d;
}
__device__ __forceinline__ float blo(u32 h) { return __uint_as_float(h << 16); }
__device__ __forceinline__ float bhi(u32 h) { return __uint_as_float(h & 0xffff0000u); }
__device__ __forceinline__ void split2(float a, float b, u32& h, u32& l) {
    h = cvt2(b, a);
    l = cvt2(b - bhi(h), a - blo(h));
}
__device__ __forceinline__ u32 smaddr(const void* p) {
    u32 r;
    asm("{ .reg .u64 t; cvta.to.shared.u64 t, %1; cvt.u32.u64 %0, t; }" : "=r"(r) : "l"(p));
    return r;
}
__device__ __forceinline__ void ldsm4(u32* r, u32 a) {
    asm volatile("ldmatrix.sync.aligned.m8n8.x4.shared.b16 {%0,%1,%2,%3}, [%4];"
        : "=r"(r[0]), "=r"(r[1]), "=r"(r[2]), "=r"(r[3]) : "r"(a));
}
__device__ __forceinline__ void ldsm4t(u32* r, u32 a) {
    asm volatile("ldmatrix.sync.aligned.m8n8.x4.trans.shared.b16 {%0,%1,%2,%3}, [%4];"
        : "=r"(r[0]), "=r"(r[1]), "=r"(r[2]), "=r"(r[3]) : "r"(a));
}
__device__ __forceinline__ void hmma(float* c, const u32* a, const u32* b) {
    asm volatile(
        "mma.sync.aligned.m16n8k16.row.col.f32.bf16.bf16.f32 "
        "{%0,%1,%2,%3}, {%4,%5,%6,%7}, {%8,%9}, {%0,%1,%2,%3};"
        : "+f"(c[0]), "+f"(c[1]), "+f"(c[2]), "+f"(c[3])
        : "r"(a[0]), "r"(a[1]), "r"(a[2]), "r"(a[3]), "r"(b[0]), "r"(b[1]));
}

// scratch
__device__ float g_kv_part[BB * HH * SPLITS * 64 * 64];
__device__ u32   g_Mh[BB * HH * 64 * 32];
__device__ u32   g_Ml[BB * HH * 64 * 32];
__device__ float g_tabc[BB * NN * 32];
__device__ float g_tabs[BB * NN * 32];

// ============== tab kernel ==============
__global__ __launch_bounds__(256)
void tab_kernel(const float* __restrict__ pos)
{
    int idx = blockIdx.x * 256 + threadIdx.x;
    float f = pos[idx >> 5] * 64.f * exp2f(-(float)(idx & 31) * L2_10K);
    float s_, c_;
    sincosf(f, &s_, &c_);
    g_tabc[idx] = c_;
    g_tabs[idx] = s_;
}

// ============== kv kernel (frozen from R7) ==============
__global__ __launch_bounds__(256, 3)
void kv_kernel(const float* __restrict__ x,
               const float* __restrict__ Wk, const float* __restrict__ Wv)
{
    extern __shared__ float sm[];
    float* xs = sm;
    float* ks = sm + CT * XSS;
    float* wk = sm + 2 * CT * XSS;
    float* wv = wk + 4096;

    const int tid = threadIdx.x;
    const int b = blockIdx.z, h = blockIdx.y, s = blockIdx.x;

    #pragma unroll
    for (int r = 0; r < 16; r++) {
        int idx = tid + r * 256;
        int i = idx >> 6, o = idx & 63;
        wk[idx] = Wk[i * 512 + h * 64 + o];
        wv[idx] = Wv[i * 512 + h * 64 + o];
    }

    const bool kwarp = (tid < 128);
    const int local = tid & 127;
    const int lane = local & 31;
    const int wl = local >> 5;
    const int og = lane >> 2;
    const int tl = lane & 3;
    const int tg = wl * 4 + tl;
    const int o0 = og * 8;
    const float* W = kwarp ? wk : wv;
    float* dstbuf = kwarp ? ks : xs;
    const float sgn = (og < 4) ? -1.f : 1.f;
    const u64 sgn2 = pk2(sgn, sgn);
    const int fbase = o0 & 31;

    const int lane8 = tid & 31;
    const int eg = lane8 >> 2;
    const int dg = (tid >> 5) * 4 + (lane8 & 3);
    const int d0 = dg * 2;
    const int e0 = eg * 8;
    u64 kva[2][4];
    #pragma unroll
    for (int dj = 0; dj < 2; dj++)
        #pragma unroll
        for (int p = 0; p < 4; p++) kva[dj][p] = 0ull;

    __syncthreads();

    const int tok_per_blk = NN / SPLITS;
    #pragma unroll 1
    for (int c = 0; c < tok_per_blk / CT; c++) {
        const int tbase = s * tok_per_blk + c * CT;
        const float* xg = x + ((size_t)b * NN + tbase) * 64;

        __syncthreads();
        #pragma unroll
        for (int r = 0; r < 16; r++) {
            int idx = tid + r * 256;
            xs[(idx >> 6) * XSS + (idx & 63)] = xg[idx];
        }
        __syncthreads();

        u64 acc[4][4];
        #pragma unroll
        for (int j = 0; j < 4; j++)
            #pragma unroll
            for (int p = 0; p < 4; p++) acc[j][p] = 0ull;

        #pragma unroll 2
        for (int i2 = 0; i2 < 32; i2++) {
            const int i = 2 * i2;
            ulonglong2 wa0 = *(const ulonglong2*)&W[i * 64 + o0];
            ulonglong2 wa1 = *(const ulonglong2*)&W[i * 64 + o0 + 4];
            ulonglong2 wb0 = *(const ulonglong2*)&W[(i + 1) * 64 + o0];
            ulonglong2 wb1 = *(const ulonglong2*)&W[(i + 1) * 64 + o0 + 4];
            u64 w0[4] = { wa0.x, wa0.y, wa1.x, wa1.y };
            u64 w1[4] = { wb0.x, wb0.y, wb1.x, wb1.y };
            #pragma unroll
            for (int j = 0; j < 4; j++) {
                u64 xp = *(const u64*)&xs[(tg + 16 * j) * XSS + i];
                float2 xf = up2(xp);
                u64 xl = pk2(xf.x, xf.x);
                u64 xh = pk2(xf.y, xf.y);
                #pragma unroll
                for (int p = 0; p < 4; p++) {
                    fma2(acc[j][p], xl, w0[p]);
                    fma2(acc[j][p], xh, w1[p]);
                }
            }
        }
        __syncthreads();

        #pragma unroll
        for (int j = 0; j < 4; j++) {
            const int t = tg + 16 * j;
            u64 t01 = add2(acc[j][0], acc[j][1]);
            u64 t23 = add2(acc[j][2], acc[j][3]);
            float2 sf = up2(add2(t01, t23));
            float s1 = sf.x + sf.y;
            u64 q01 = add2(mul2(acc[j][0], acc[j][0]), mul2(acc[j][1], acc[j][1]));
            u64 q23 = add2(mul2(acc[j][2], acc[j][2]), mul2(acc[j][3], acc[j][3]));
            float2 qf = up2(add2(q01, q23));
            float s2 = qf.x + qf.y;
            #pragma unroll
            for (int m = 4; m <= 16; m <<= 1) {
                s1 += __shfl_xor_sync(0xffffffffu, s1, m);
                s2 += __shfl_xor_sync(0xffffffffu, s2, m);
            }
            float mean = s1 * (1.f / 64.f);
            float var = fmaxf(s2 * (1.f / 64.f) - mean * mean, 0.f);
            float rs = rsqrtf(var + 1e-5f);
            float mr = -mean * rs;
            u64 rs2 = pk2(rs, rs), mr2 = pk2(mr, mr);
            u64 kn[4];
            #pragma unroll
            for (int p = 0; p < 4; p++) { kn[p] = mr2; fma2(kn[p], acc[j][p], rs2); }

            if (kwarp) {
                u64 pn[4];
                #pragma unroll
                for (int p = 0; p < 4; p++)
                    pn[p] = __shfl_xor_sync(0xffffffffu, kn[p], 16);
                const float* tc = &g_tabc[((size_t)(b * NN + tbase + t)) * 32 + fbase];
                const float* ts = &g_tabs[((size_t)(b * NN + tbase + t)) * 32 + fbase];
                float4 c0 = *(const float4*)tc;
                float4 c1 = *(const float4*)(tc + 4);
                float4 s0 = *(const float4*)ts;
                float4 s1v = *(const float4*)(ts + 4);
                u64 cc[4] = { pk2(c0.x, c0.y), pk2(c0.z, c0.w),
                              pk2(c1.x, c1.y), pk2(c1.z, c1.w) };
                u64 ss[4] = { pk2(s0.x, s0.y), pk2(s0.z, s0.w),
                              pk2(s1v.x, s1v.y), pk2(s1v.z, s1v.w) };
                #pragma unroll
                for (int p = 0; p < 4; p++) {
                    u64 r = mul2(kn[p], cc[p]);
                    fma2(r, pn[p], mul2(ss[p], sgn2));
                    kn[p] = r;
                }
            }
            #pragma unroll
            for (int sr = 0; sr < 4; sr++) {
                int p = (sr + og) & 3;
                *(u64*)&dstbuf[t * XSS + o0 + 2 * p] = kn[p];
            }
        }
        __syncthreads();

        #pragma unroll 8
        for (int t = 0; t < CT; t++) {
            u64 kp = *(const u64*)&ks[t * XSS + d0];
            float2 kf = up2(kp);
            u64 kk0 = pk2(kf.x, kf.x), kk1 = pk2(kf.y, kf.y);
            ulonglong2 v0 = *(const ulonglong2*)&xs[t * XSS + e0];
            ulonglong2 v1 = *(const ulonglong2*)&xs[t * XSS + e0 + 4];
            u64 vp[4] = { v0.x, v0.y, v1.x, v1.y };
            #pragma unroll
            for (int p = 0; p < 4; p++) {
                fma2(kva[0][p], kk0, vp[p]);
                fma2(kva[1][p], kk1, vp[p]);
            }
        }
    }

    float* dst = g_kv_part + ((size_t)((b * HH + h) * SPLITS + s)) * 4096;
    #pragma unroll
    for (int dj = 0; dj < 2; dj++)
        #pragma unroll
        for (int p = 0; p < 4; p++)
            *(u64*)&dst[(d0 + dj) * 64 + e0 + 2 * p] = kva[dj][p];
}

// ============== m kernel: reduce + M=(kv@Wo)/N, emit bf16 hi/lo ==============
__global__ __launch_bounds__(256, 1)
void m_kernel(const float* __restrict__ Wo)
{
    __shared__ float kvs[64 * 66];
    __shared__ float wo[64 * 64];
    const int tid = threadIdx.x;
    const int h = blockIdx.x, b = blockIdx.y;
    const float* src = g_kv_part + (size_t)(b * HH + h) * SPLITS * 4096;

    #pragma unroll
    for (int r = 0; r < 16; r++) {
        int idx = tid + r * 256;
        float acc = 0.f;
        #pragma unroll 4
        for (int s = 0; s < SPLITS; s++) acc += src[s * 4096 + idx];
        int i = idx >> 6, j = idx & 63;
        kvs[i * 66 + j] = acc;
        wo[idx] = Wo[(h * 64 + i) * 64 + j];
    }
    __syncthreads();

    const int i0 = (tid >> 3) * 2;
    const int d0 = (tid & 7) * 8;
    u64 a[2][4];
    #pragma unroll
    for (int ij = 0; ij < 2; ij++)
        #pragma unroll
        for (int p = 0; p < 4; p++) a[ij][p] = 0ull;

    #pragma unroll 8
    for (int j = 0; j < 64; j++) {
        float k0 = kvs[i0 * 66 + j], k1 = kvs[(i0 + 1) * 66 + j];
        u64 p0 = pk2(k0, k0), p1 = pk2(k1, k1);
        ulonglong2 w0 = *(const ulonglong2*)&wo[j * 64 + d0];
        ulonglong2 w1 = *(const ulonglong2*)&wo[j * 64 + d0 + 4];
        u64 wp[4] = { w0.x, w0.y, w1.x, w1.y };
        #pragma unroll
        for (int p = 0; p < 4; p++) {
            fma2(a[0][p], p0, wp[p]);
            fma2(a[1][p], p1, wp[p]);
        }
    }
    const float sc = 1.f / (float)NN;
    const u64 sc2 = pk2(sc, sc);
    const int mbase = (b * HH + h) * 64 * 32;
    #pragma unroll
    for (int ij = 0; ij < 2; ij++)
        #pragma unroll
        for (int p = 0; p < 4; p++) {
            float2 v = up2(mul2(a[ij][p], sc2));
            u32 hh, ll;
            split2(v.x, v.y, hh, ll);
            int idx = mbase + (i0 + ij) * 32 + (d0 >> 1) + p;
            g_Mh[idx] = hh;
            g_Ml[idx] = ll;
        }
}

// ============== out kernel: bf16 mma, 3-pass split ==============
// smem halves: xbh[128*72] xbl[128*72] wh[64*72] wl[64*72] mh[64*72] ml[64*72]
__global__ __launch_bounds__(256, 2)
void out_kernel(const float* __restrict__ x,
                const float* __restrict__ Wq, float* __restrict__ out)
{
    extern __shared__ __align__(16) unsigned short sh[];
    unsigned short* xbh = sh;
    unsigned short* xbl = xbh + 128 * 72;
    unsigned short* whs = xbl + 128 * 72;
    unsigned short* wls = whs + 64 * 72;
    unsigned short* mhs = wls + 64 * 72;
    unsigned short* mls = mhs + 64 * 72;

    const int tid = threadIdx.x;
    const int b = blockIdx.y;
    const int tbase = blockIdx.x * OCT;
    const int w = tid >> 5, lane = tid & 31;
    const int g = lane >> 2, tc4 = lane & 3;
    const int rb = w * 16;
    const int lr = lane & 15, lc = (lane >> 4) * 8;

    // stage x split-bf16
    const float* xg = x + ((size_t)b * NN + tbase) * 64;
    #pragma unroll
    for (int r = 0; r < 16; r++) {
        int p = tid + r * 256;           // 4096 float2 pairs
        int t = p >> 5, ip = (p & 31) * 2;
        float2 v = *(const float2*)&xg[t * 64 + ip];
        u32 hh, ll;
        split2(v.x, v.y, hh, ll);
        *(u32*)&xbh[t * 72 + ip] = hh;
        *(u32*)&xbl[t * 72 + ip] = ll;
    }

    float oc[8][4];
    #pragma unroll
    for (int nb = 0; nb < 8; nb++)
        #pragma unroll
        for (int e = 0; e < 4; e++) oc[nb][e] = 0.f;

    const size_t trow = (size_t)b * NN + tbase + rb + g;
    const float* tcb = &g_tabc[trow * 32 + 2 * tc4];
    const float* tsb = &g_tabs[trow * 32 + 2 * tc4];

    #pragma unroll 1
    for (int hh8 = 0; hh8 < HH; hh8++) {
        const int mbase = (b * HH + hh8) * 64 * 32;
        #pragma unroll
        for (int r = 0; r < 8; r++) {
            int p = tid + r * 256;       // 2048 pairs
            int i = p >> 5, op = (p & 31) * 2;
            float2 wv = *(const float2*)&Wq[i * 512 + hh8 * 64 + op];
            u32 whv, wlv;
            split2(wv.x, wv.y, whv, wlv);
            *(u32*)&whs[i * 72 + op] = whv;
            *(u32*)&wls[i * 72 + op] = wlv;
            *(u32*)&mhs[i * 72 + op] = g_Mh[mbase + i * 32 + (op >> 1)];
            *(u32*)&mls[i * 72 + op] = g_Ml[mbase + i * 32 + (op >> 1)];
        }
        __syncthreads();

        // GEMM1: q = x @ Wq_h (3-pass)
        float qc[8][4];
        #pragma unroll
        for (int nb = 0; nb < 8; nb++)
            #pragma unroll
            for (int e = 0; e < 4; e++) qc[nb][e] = 0.f;

        #pragma unroll
        for (int kb = 0; kb < 4; kb++) {
            u32 ah[4], al[4];
            ldsm4(ah, smaddr(&xbh[(rb + lr) * 72 + kb * 16 + lc]));
            ldsm4(al, smaddr(&xbl[(rb + lr) * 72 + kb * 16 + lc]));
            #pragma unroll
            for (int nb2 = 0; nb2 < 4; nb2++) {
                u32 bh[4], bl[4];
                ldsm4t(bh, smaddr(&whs[(kb * 16 + lr) * 72 + nb2 * 16 + lc]));
                ldsm4t(bl, smaddr(&wls[(kb * 16 + lr) * 72 + nb2 * 16 + lc]));
                hmma(qc[2 * nb2],     ah, &bh[0]);
                hmma(qc[2 * nb2],     al, &bh[0]);
                hmma(qc[2 * nb2],     ah, &bl[0]);
                hmma(qc[2 * nb2 + 1], ah, &bh[2]);
                hmma(qc[2 * nb2 + 1], al, &bh[2]);
                hmma(qc[2 * nb2 + 1], ah, &bl[2]);
            }
        }

        // RoPE on q fragments (col c pairs with c+32 => nb with nb+4)
        #pragma unroll
        for (int nb = 0; nb < 4; nb++) {
            float2 c0 = *(const float2*)(tcb + 8 * nb);
            float2 c1 = *(const float2*)(tcb + 256 + 8 * nb);
            float2 s0 = *(const float2*)(tsb + 8 * nb);
            float2 s1 = *(const float2*)(tsb + 256 + 8 * nb);
            float cs[4] = { c0.x, c0.y, c1.x, c1.y };
            float sn[4] = { s0.x, s0.y, s1.x, s1.y };
            #pragma unroll
            for (int e = 0; e < 4; e++) {
                float lo = qc[nb][e], hi = qc[nb + 4][e];
                qc[nb][e]     = lo * cs[e] - hi * sn[e];
                qc[nb + 4][e] = hi * cs[e] + lo * sn[e];
            }
        }

        // GEMM2: out += q @ M_h (A in registers, 3-pass)
        #pragma unroll
        for (int kb = 0; kb < 4; kb++) {
            u32 qah[4], qal[4];
            split2(qc[2 * kb][0],     qc[2 * kb][1],     qah[0], qal[0]);
            split2(qc[2 * kb][2],     qc[2 * kb][3],     qah[1], qal[1]);
            split2(qc[2 * kb + 1][0], qc[2 * kb + 1][1], qah[2], qal[2]);
            split2(qc[2 * kb + 1][2], qc[2 * kb + 1][3], qah[3], qal[3]);
            #pragma unroll
            for (int nb2 = 0; nb2 < 4; nb2++) {
                u32 bh[4], bl[4];
                ldsm4t(bh, smaddr(&mhs[(kb * 16 + lr) * 72 + nb2 * 16 + lc]));
                ldsm4t(bl, smaddr(&mls[(kb * 16 + lr) * 72 + nb2 * 16 + lc]));
                hmma(oc[2 * nb2],     qah, &bh[0]);
                hmma(oc[2 * nb2],     qal, &bh[0]);
                hmma(oc[2 * nb2],     qah, &bl[0]);
                hmma(oc[2 * nb2 + 1], qah, &bh[2]);
                hmma(oc[2 * nb2 + 1], qal, &bh[2]);
                hmma(oc[2 * nb2 + 1], qah, &bl[2]);
            }
        }
        __syncthreads();
    }

    float* outg = out + ((size_t)b * NN + tbase + rb) * 64;
    #pragma unroll
    for (int nb = 0; nb < 8; nb++) {
        float2 v0 = { oc[nb][0], oc[nb][1] };
        float2 v1 = { oc[nb][2], oc[nb][3] };
        *(float2*)&outg[g * 64 + 8 * nb + 2 * tc4]       = v0;
        *(float2*)&outg[(g + 8) * 64 + 8 * nb + 2 * tc4] = v1;
    }
}

// =====================================================================
extern "C" void kernel_launch(void* const* d_in, const int* in_sizes, int n_in,
                              void* d_out, int out_size)
{
    const float* x   = (const float*)d_in[0];
    const float* pos = (const float*)d_in[1];
    const float* Wq  = (const float*)d_in[2];
    const float* Wk  = (const float*)d_in[3];
    const float* Wv  = (const float*)d_in[4];
    const float* Wo  = (const float*)d_in[5];
    float* out = (float*)d_out;

    const int SMEM_KV  = (2 * CT * XSS + 2 * 4096) * 4;     // 67584 B
    const int SMEM_OUT = (2 * 128 * 72 + 4 * 64 * 72) * 2;  // 73728 B
    cudaFuncSetAttribute(kv_kernel,  cudaFuncAttributeMaxDynamicSharedMemorySize, SMEM_KV);
    cudaFuncSetAttribute(out_kernel, cudaFuncAttributeMaxDynamicSharedMemorySize, SMEM_OUT);

    tab_kernel<<<BB * NN * 32 / 256, 256>>>(pos);
    kv_kernel<<<dim3(SPLITS, HH, BB), 256, SMEM_KV>>>(x, Wk, Wv);
    m_kernel<<<dim3(HH, BB), 256>>>(Wo);
    out_kernel<<<dim3(NN / OCT, BB), 256, SMEM_OUT>>>(x, Wq, out);
}

// round 12
// speedup vs baseline: 1.4703x; 1.0260x over previous
#include <cuda_runtime.h>
#include <math.h>

#define BB 4
#define NN 16384
#define HH 8
#define SPLITS 64
#define KCT 64
#define OCT 128
#define L2_10K 0.4152410118609203f

typedef unsigned long long u64;
typedef unsigned int u32;
typedef unsigned short ush;

__device__ __forceinline__ u64 pk2(float a, float b) {
    u64 r;
    asm("mov.b64 %0, {%1, %2};" : "=l"(r)
        : "r"(__float_as_uint(a)), "r"(__float_as_uint(b)));
    return r;
}
__device__ __forceinline__ float2 up2(u64 a) {
    unsigned int lo, hi;
    asm("mov.b64 {%0, %1}, %2;" : "=r"(lo), "=r"(hi) : "l"(a));
    float2 r; r.x = __uint_as_float(lo); r.y = __uint_as_float(hi);
    return r;
}
__device__ __forceinline__ void fma2(u64& d, u64 a, u64 b) {
    asm("fma.rn.f32x2 %0, %1, %2, %0;" : "+l"(d) : "l"(a), "l"(b));
}
__device__ __forceinline__ u64 mul2(u64 a, u64 b) {
    u64 r; asm("mul.rn.f32x2 %0, %1, %2;" : "=l"(r) : "l"(a), "l"(b)); return r;
}

// bf16 helpers
__device__ __forceinline__ u32 cvt2(float hi, float lo) {
    u32 d; asm("cvt.rn.bf16x2.f32 %0, %1, %2;" : "=r"(d) : "f"(hi), "f"(lo));
    return d;
}
__device__ __forceinline__ float blo(u32 h) { return __uint_as_float(h << 16); }
__device__ __forceinline__ float bhi(u32 h) { return __uint_as_float(h & 0xffff0000u); }
__device__ __forceinline__ void split2(float a, float b, u32& h, u32& l) {
    h = cvt2(b, a);
    l = cvt2(b - bhi(h), a - blo(h));
}
__device__ __forceinline__ u32 smaddr(const void* p) {
    u32 r;
    asm("{ .reg .u64 t; cvta.to.shared.u64 t, %1; cvt.u32.u64 %0, t; }" : "=r"(r) : "l"(p));
    return r;
}
__device__ __forceinline__ void ldsm4(u32* r, u32 a) {
    asm volatile("ldmatrix.sync.aligned.m8n8.x4.shared.b16 {%0,%1,%2,%3}, [%4];"
        : "=r"(r[0]), "=r"(r[1]), "=r"(r[2]), "=r"(r[3]) : "r"(a));
}
__device__ __forceinline__ void ldsm4t(u32* r, u32 a) {
    asm volatile("ldmatrix.sync.aligned.m8n8.x4.trans.shared.b16 {%0,%1,%2,%3}, [%4];"
        : "=r"(r[0]), "=r"(r[1]), "=r"(r[2]), "=r"(r[3]) : "r"(a));
}
__device__ __forceinline__ void hmma(float* c, const u32* a, const u32* b) {
    asm volatile(
        "mma.sync.aligned.m16n8k16.row.col.f32.bf16.bf16.f32 "
        "{%0,%1,%2,%3}, {%4,%5,%6,%7}, {%8,%9}, {%0,%1,%2,%3};"
        : "+f"(c[0]), "+f"(c[1]), "+f"(c[2]), "+f"(c[3])
        : "r"(a[0]), "r"(a[1]), "r"(a[2]), "r"(a[3]), "r"(b[0]), "r"(b[1]));
}

// scratch
__device__ float g_kv_part[BB * HH * SPLITS * 64 * 64];
__device__ u32   g_Mh[BB * HH * 64 * 32];
__device__ u32   g_Ml[BB * HH * 64 * 32];
__device__ float g_tabc[BB * NN * 32];
__device__ float g_tabs[BB * NN * 32];

// ============== tab kernel ==============
__global__ __launch_bounds__(256)
void tab_kernel(const float* __restrict__ pos)
{
    int idx = blockIdx.x * 256 + threadIdx.x;
    float f = pos[idx >> 5] * 64.f * exp2f(-(float)(idx & 31) * L2_10K);
    float s_, c_;
    sincosf(f, &s_, &c_);
    g_tabc[idx] = c_;
    g_tabs[idx] = s_;
}

// ============== kv kernel: bf16 mma, 3-pass split ==============
// per (b,h,s): 4 chunks of 64 tokens.
// smem halves: xk hi/lo [64*72]x2 (x, then k) | v hi/lo [64*72]x2 |
//              W hi [2][64*72] | W lo [2][64*72]  = 36864 halves = 73728 B
__global__ __launch_bounds__(256, 2)
void kv_kernel(const float* __restrict__ x,
               const float* __restrict__ Wk, const float* __restrict__ Wv)
{
    extern __shared__ __align__(16) ush sh[];
    ush* xkh = sh;              // 4608 halves
    ush* xkl = sh + 4608;
    ush* vhs = sh + 9216;
    ush* vls = sh + 13824;
    ush* whb = sh + 18432;      // [sel][64*72]
    ush* wlb = sh + 27648;

    const int tid = threadIdx.x;
    const int b = blockIdx.z, h = blockIdx.y, s = blockIdx.x;
    const int w = tid >> 5, lane = tid & 31;
    const int g = lane >> 2, tc4 = lane & 3;
    const int lr = lane & 15, lc = (lane >> 4) * 8;
    const bool kwarp = (w < 4);
    const int mb = w & 3, rb = mb * 16;
    // GEMM2 tiling: warp owns d-block md (16 rows), cols nhalf*32..+31
    const int md = w & 3, nhalf = w >> 2;

    // stage Wk/Wv split-bf16
    #pragma unroll
    for (int r = 0; r < 16; r++) {
        int p = tid + r * 256;            // [0,4096) pairs
        int sel = p >> 11;
        int q = p & 2047;
        int i = q >> 5, op = (q & 31) * 2;
        const float* Ws = sel ? Wv : Wk;
        float2 wv2 = *(const float2*)&Ws[i * 512 + h * 64 + op];
        u32 hh, ll;
        split2(wv2.x, wv2.y, hh, ll);
        *(u32*)&whb[sel * 4608 + i * 72 + op] = hh;
        *(u32*)&wlb[sel * 4608 + i * 72 + op] = ll;
    }

    const ush* WH = whb + (kwarp ? 0 : 4608);
    const ush* WL = wlb + (kwarp ? 0 : 4608);
    ush* DH = kwarp ? xkh : vhs;
    ush* DL = kwarp ? xkl : vls;

    float kvc[4][4];
    #pragma unroll
    for (int i = 0; i < 4; i++)
        #pragma unroll
        for (int e = 0; e < 4; e++) kvc[i][e] = 0.f;

    #pragma unroll 1
    for (int c = 0; c < 4; c++) {
        const int tbase = s * 256 + c * KCT;
        __syncthreads();     // prior GEMM2 reads of xk/v done (also covers W staging)

        // stage x split-bf16 (64 tokens)
        const float* xg = x + ((size_t)b * NN + tbase) * 64;
        #pragma unroll
        for (int r = 0; r < 8; r++) {
            int p = tid + r * 256;        // [0,2048) pairs
            int t = p >> 5, ip = (p & 31) * 2;
            float2 v = *(const float2*)&xg[t * 64 + ip];
            u32 hh, ll;
            split2(v.x, v.y, hh, ll);
            *(u32*)&xkh[t * 72 + ip] = hh;
            *(u32*)&xkl[t * 72 + ip] = ll;
        }
        __syncthreads();

        // GEMM1: proj 16 rows x 64 cols per warp (k or v), 3-pass
        float pc[8][4];
        #pragma unroll
        for (int nb = 0; nb < 8; nb++)
            #pragma unroll
            for (int e = 0; e < 4; e++) pc[nb][e] = 0.f;

        #pragma unroll
        for (int kb = 0; kb < 4; kb++) {
            u32 ah[4], al[4];
            ldsm4(ah, smaddr(&xkh[(rb + lr) * 72 + kb * 16 + lc]));
            ldsm4(al, smaddr(&xkl[(rb + lr) * 72 + kb * 16 + lc]));
            #pragma unroll
            for (int nl = 0; nl < 4; nl++) {
                u32 bh[4], bl[4];
                ldsm4t(bh, smaddr(&WH[(kb * 16 + lr) * 72 + nl * 16 + lc]));
                ldsm4t(bl, smaddr(&WL[(kb * 16 + lr) * 72 + nl * 16 + lc]));
                hmma(pc[2 * nl],     ah, &bh[0]);
                hmma(pc[2 * nl],     al, &bh[0]);
                hmma(pc[2 * nl],     ah, &bl[0]);
                hmma(pc[2 * nl + 1], ah, &bh[2]);
                hmma(pc[2 * nl + 1], al, &bh[2]);
                hmma(pc[2 * nl + 1], ah, &bl[2]);
            }
        }
        __syncthreads();     // x reads done before overwrite with k

        // LayerNorm: rows rb+g (elems 0,1) and rb+g+8 (elems 2,3)
        float s1a = 0.f, s2a = 0.f, s1b = 0.f, s2b = 0.f;
        #pragma unroll
        for (int nb = 0; nb < 8; nb++) {
            s1a += pc[nb][0] + pc[nb][1];
            s2a += pc[nb][0] * pc[nb][0] + pc[nb][1] * pc[nb][1];
            s1b += pc[nb][2] + pc[nb][3];
            s2b += pc[nb][2] * pc[nb][2] + pc[nb][3] * pc[nb][3];
        }
        #pragma unroll
        for (int m = 1; m < 4; m <<= 1) {
            s1a += __shfl_xor_sync(0xffffffffu, s1a, m);
            s2a += __shfl_xor_sync(0xffffffffu, s2a, m);
            s1b += __shfl_xor_sync(0xffffffffu, s1b, m);
            s2b += __shfl_xor_sync(0xffffffffu, s2b, m);
        }
        float ma = s1a * (1.f / 64.f);
        float ra = rsqrtf(fmaxf(s2a * (1.f / 64.f) - ma * ma, 0.f) + 1e-5f);
        float mb_ = s1b * (1.f / 64.f);
        float rbn = rsqrtf(fmaxf(s2b * (1.f / 64.f) - mb_ * mb_, 0.f) + 1e-5f);
        #pragma unroll
        for (int nb = 0; nb < 8; nb++) {
            pc[nb][0] = (pc[nb][0] - ma) * ra;
            pc[nb][1] = (pc[nb][1] - ma) * ra;
            pc[nb][2] = (pc[nb][2] - mb_) * rbn;
            pc[nb][3] = (pc[nb][3] - mb_) * rbn;
        }

        if (kwarp) {   // RoPE on k: col c <-> c+32 == nb <-> nb+4
            const size_t tr = (size_t)b * NN + tbase + rb + g;
            const float* tcb = &g_tabc[tr * 32 + 2 * tc4];
            const float* tsb = &g_tabs[tr * 32 + 2 * tc4];
            #pragma unroll
            for (int nb = 0; nb < 4; nb++) {
                float2 c0 = *(const float2*)(tcb + 8 * nb);
                float2 c1 = *(const float2*)(tcb + 256 + 8 * nb);
                float2 s0 = *(const float2*)(tsb + 8 * nb);
                float2 s1 = *(const float2*)(tsb + 256 + 8 * nb);
                float cs[4] = { c0.x, c0.y, c1.x, c1.y };
                float sn[4] = { s0.x, s0.y, s1.x, s1.y };
                #pragma unroll
                for (int e = 0; e < 4; e++) {
                    float lo = pc[nb][e], hi = pc[nb + 4][e];
                    pc[nb][e]     = lo * cs[e] - hi * sn[e];
                    pc[nb + 4][e] = hi * cs[e] + lo * sn[e];
                }
            }
        }

        // store split-bf16 k/v
        #pragma unroll
        for (int nb = 0; nb < 8; nb++) {
            u32 hh, ll;
            split2(pc[nb][0], pc[nb][1], hh, ll);
            *(u32*)&DH[(rb + g) * 72 + 8 * nb + 2 * tc4] = hh;
            *(u32*)&DL[(rb + g) * 72 + 8 * nb + 2 * tc4] = ll;
            split2(pc[nb][2], pc[nb][3], hh, ll);
            *(u32*)&DH[(rb + g + 8) * 72 + 8 * nb + 2 * tc4] = hh;
            *(u32*)&DL[(rb + g + 8) * 72 + 8 * nb + 2 * tc4] = ll;
        }
        __syncthreads();

        // GEMM2: kv[d][e] += k^T v  (A via trans from [t][d]: perm {0,2,1,3})
        #pragma unroll
        for (int kt = 0; kt < 4; kt++) {
            u32 t0[4], t1[4];
            ldsm4t(t0, smaddr(&xkh[(kt * 16 + lr) * 72 + md * 16 + lc]));
            ldsm4t(t1, smaddr(&xkl[(kt * 16 + lr) * 72 + md * 16 + lc]));
            u32 ah[4] = { t0[0], t0[2], t0[1], t0[3] };
            u32 al[4] = { t1[0], t1[2], t1[1], t1[3] };
            #pragma unroll
            for (int nl = 0; nl < 2; nl++) {
                u32 bh[4], bl[4];
                ldsm4t(bh, smaddr(&vhs[(kt * 16 + lr) * 72 + nhalf * 32 + nl * 16 + lc]));
                ldsm4t(bl, smaddr(&vls[(kt * 16 + lr) * 72 + nhalf * 32 + nl * 16 + lc]));
                hmma(kvc[2 * nl],     ah, &bh[0]);
                hmma(kvc[2 * nl],     al, &bh[0]);
                hmma(kvc[2 * nl],     ah, &bl[0]);
                hmma(kvc[2 * nl + 1], ah, &bh[2]);
                hmma(kvc[2 * nl + 1], al, &bh[2]);
                hmma(kvc[2 * nl + 1], ah, &bl[2]);
            }
        }
    }

    // epilogue: fp32 partial kv
    float* dst = g_kv_part + ((size_t)((b * HH + h) * SPLITS + s)) * 4096;
    const int d0 = md * 16 + g;
    #pragma unroll
    for (int nb = 0; nb < 4; nb++) {
        int col = nhalf * 32 + 8 * nb + 2 * tc4;
        float2 v0 = { kvc[nb][0], kvc[nb][1] };
        float2 v1 = { kvc[nb][2], kvc[nb][3] };
        *(float2*)&dst[d0 * 64 + col]       = v0;
        *(float2*)&dst[(d0 + 8) * 64 + col] = v1;
    }
}

// ============== m kernel: reduce + M=(kv@Wo)/N, emit bf16 hi/lo ==============
__global__ __launch_bounds__(256, 1)
void m_kernel(const float* __restrict__ Wo)
{
    __shared__ float kvs[64 * 66];
    __shared__ float wo[64 * 64];
    const int tid = threadIdx.x;
    const int h = blockIdx.x, b = blockIdx.y;
    const float* src = g_kv_part + (size_t)(b * HH + h) * SPLITS * 4096;

    #pragma unroll
    for (int r = 0; r < 16; r++) {
        int idx = tid + r * 256;
        float acc = 0.f;
        #pragma unroll 4
        for (int s = 0; s < SPLITS; s++) acc += src[s * 4096 + idx];
        int i = idx >> 6, j = idx & 63;
        kvs[i * 66 + j] = acc;
        wo[idx] = Wo[(h * 64 + i) * 64 + j];
    }
    __syncthreads();

    const int i0 = (tid >> 3) * 2;
    const int d0 = (tid & 7) * 8;
    u64 a[2][4];
    #pragma unroll
    for (int ij = 0; ij < 2; ij++)
        #pragma unroll
        for (int p = 0; p < 4; p++) a[ij][p] = 0ull;

    #pragma unroll 8
    for (int j = 0; j < 64; j++) {
        float k0 = kvs[i0 * 66 + j], k1 = kvs[(i0 + 1) * 66 + j];
        u64 p0 = pk2(k0, k0), p1 = pk2(k1, k1);
        ulonglong2 w0 = *(const ulonglong2*)&wo[j * 64 + d0];
        ulonglong2 w1 = *(const ulonglong2*)&wo[j * 64 + d0 + 4];
        u64 wp[4] = { w0.x, w0.y, w1.x, w1.y };
        #pragma unroll
        for (int p = 0; p < 4; p++) {
            fma2(a[0][p], p0, wp[p]);
            fma2(a[1][p], p1, wp[p]);
        }
    }
    const float sc = 1.f / (float)NN;
    const u64 sc2 = pk2(sc, sc);
    const int mbase = (b * HH + h) * 64 * 32;
    #pragma unroll
    for (int ij = 0; ij < 2; ij++)
        #pragma unroll
        for (int p = 0; p < 4; p++) {
            float2 v = up2(mul2(a[ij][p], sc2));
            u32 hh, ll;
            split2(v.x, v.y, hh, ll);
            int idx = mbase + (i0 + ij) * 32 + (d0 >> 1) + p;
            g_Mh[idx] = hh;
            g_Ml[idx] = ll;
        }
}

// ============== out kernel (frozen from R9): bf16 mma, 3-pass ==============
__global__ __launch_bounds__(256, 2)
void out_kernel(const float* __restrict__ x,
                const float* __restrict__ Wq, float* __restrict__ out)
{
    extern __shared__ __align__(16) ush sh[];
    ush* xbh = sh;
    ush* xbl = xbh + 128 * 72;
    ush* whs = xbl + 128 * 72;
    ush* wls = whs + 64 * 72;
    ush* mhs = wls + 64 * 72;
    ush* mls = mhs + 64 * 72;

    const int tid = threadIdx.x;
    const int b = blockIdx.y;
    const int tbase = blockIdx.x * OCT;
    const int w = tid >> 5, lane = tid & 31;
    const int g = lane >> 2, tc4 = lane & 3;
    const int rb = w * 16;
    const int lr = lane & 15, lc = (lane >> 4) * 8;

    const float* xg = x + ((size_t)b * NN + tbase) * 64;
    #pragma unroll
    for (int r = 0; r < 16; r++) {
        int p = tid + r * 256;
        int t = p >> 5, ip = (p & 31) * 2;
        float2 v = *(const float2*)&xg[t * 64 + ip];
        u32 hh, ll;
        split2(v.x, v.y, hh, ll);
        *(u32*)&xbh[t * 72 + ip] = hh;
        *(u32*)&xbl[t * 72 + ip] = ll;
    }

    float oc[8][4];
    #pragma unroll
    for (int nb = 0; nb < 8; nb++)
        #pragma unroll
        for (int e = 0; e < 4; e++) oc[nb][e] = 0.f;

    const size_t trow = (size_t)b * NN + tbase + rb + g;
    const float* tcb = &g_tabc[trow * 32 + 2 * tc4];
    const float* tsb = &g_tabs[trow * 32 + 2 * tc4];

    #pragma unroll 1
    for (int hh8 = 0; hh8 < HH; hh8++) {
        const int mbase = (b * HH + hh8) * 64 * 32;
        #pragma unroll
        for (int r = 0; r < 8; r++) {
            int p = tid + r * 256;
            int i = p >> 5, op = (p & 31) * 2;
            float2 wv = *(const float2*)&Wq[i * 512 + hh8 * 64 + op];
            u32 whv, wlv;
            split2(wv.x, wv.y, whv, wlv);
            *(u32*)&whs[i * 72 + op] = whv;
            *(u32*)&wls[i * 72 + op] = wlv;
            *(u32*)&mhs[i * 72 + op] = g_Mh[mbase + i * 32 + (op >> 1)];
            *(u32*)&mls[i * 72 + op] = g_Ml[mbase + i * 32 + (op >> 1)];
        }
        __syncthreads();

        float qc[8][4];
        #pragma unroll
        for (int nb = 0; nb < 8; nb++)
            #pragma unroll
            for (int e = 0; e < 4; e++) qc[nb][e] = 0.f;

        #pragma unroll
        for (int kb = 0; kb < 4; kb++) {
            u32 ah[4], al[4];
            ldsm4(ah, smaddr(&xbh[(rb + lr) * 72 + kb * 16 + lc]));
            ldsm4(al, smaddr(&xbl[(rb + lr) * 72 + kb * 16 + lc]));
            #pragma unroll
            for (int nb2 = 0; nb2 < 4; nb2++) {
                u32 bh[4], bl[4];
                ldsm4t(bh, smaddr(&whs[(kb * 16 + lr) * 72 + nb2 * 16 + lc]));
                ldsm4t(bl, smaddr(&wls[(kb * 16 + lr) * 72 + nb2 * 16 + lc]));
                hmma(qc[2 * nb2],     ah, &bh[0]);
                hmma(qc[2 * nb2],     al, &bh[0]);
                hmma(qc[2 * nb2],     ah, &bl[0]);
                hmma(qc[2 * nb2 + 1], ah, &bh[2]);
                hmma(qc[2 * nb2 + 1], al, &bh[2]);
                hmma(qc[2 * nb2 + 1], ah, &bl[2]);
            }
        }

        #pragma unroll
        for (int nb = 0; nb < 4; nb++) {
            float2 c0 = *(const float2*)(tcb + 8 * nb);
            float2 c1 = *(const float2*)(tcb + 256 + 8 * nb);
            float2 s0 = *(const float2*)(tsb + 8 * nb);
            float2 s1 = *(const float2*)(tsb + 256 + 8 * nb);
            float cs[4] = { c0.x, c0.y, c1.x, c1.y };
            float sn[4] = { s0.x, s0.y, s1.x, s1.y };
            #pragma unroll
            for (int e = 0; e < 4; e++) {
                float lo = qc[nb][e], hi = qc[nb + 4][e];
                qc[nb][e]     = lo * cs[e] - hi * sn[e];
                qc[nb + 4][e] = hi * cs[e] + lo * sn[e];
            }
        }

        #pragma unroll
        for (int kb = 0; kb < 4; kb++) {
            u32 qah[4], qal[4];
            split2(qc[2 * kb][0],     qc[2 * kb][1],     qah[0], qal[0]);
            split2(qc[2 * kb][2],     qc[2 * kb][3],     qah[1], qal[1]);
            split2(qc[2 * kb + 1][0], qc[2 * kb + 1][1], qah[2], qal[2]);
            split2(qc[2 * kb + 1][2], qc[2 * kb + 1][3], qah[3], qal[3]);
            #pragma unroll
            for (int nb2 = 0; nb2 < 4; nb2++) {
                u32 bh[4], bl[4];
                ldsm4t(bh, smaddr(&mhs[(kb * 16 + lr) * 72 + nb2 * 16 + lc]));
                ldsm4t(bl, smaddr(&mls[(kb * 16 + lr) * 72 + nb2 * 16 + lc]));
                hmma(oc[2 * nb2],     qah, &bh[0]);
                hmma(oc[2 * nb2],     qal, &bh[0]);
                hmma(oc[2 * nb2],     qah, &bl[0]);
                hmma(oc[2 * nb2 + 1], qah, &bh[2]);
                hmma(oc[2 * nb2 + 1], qal, &bh[2]);
                hmma(oc[2 * nb2 + 1], qah, &bl[2]);
            }
        }
        __syncthreads();
    }

    float* outg = out + ((size_t)b * NN + tbase + rb) * 64;
    #pragma unroll
    for (int nb = 0; nb < 8; nb++) {
        float2 v0 = { oc[nb][0], oc[nb][1] };
        float2 v1 = { oc[nb][2], oc[nb][3] };
        *(float2*)&outg[g * 64 + 8 * nb + 2 * tc4]       = v0;
        *(float2*)&outg[(g + 8) * 64 + 8 * nb + 2 * tc4] = v1;
    }
}

// =====================================================================
extern "C" void kernel_launch(void* const* d_in, const int* in_sizes, int n_in,
                              void* d_out, int out_size)
{
    const float* x   = (const float*)d_in[0];
    const float* pos = (const float*)d_in[1];
    const float* Wq  = (const float*)d_in[2];
    const float* Wk  = (const float*)d_in[3];
    const float* Wv  = (const float*)d_in[4];
    const float* Wo  = (const float*)d_in[5];
    float* out = (float*)d_out;

    const int SMEM_KV  = 36864 * 2;                         // 73728 B
    const int SMEM_OUT = (2 * 128 * 72 + 4 * 64 * 72) * 2;  // 73728 B
    cudaFuncSetAttribute(kv_kernel,  cudaFuncAttributeMaxDynamicSharedMemorySize, SMEM_KV);
    cudaFuncSetAttribute(out_kernel, cudaFuncAttributeMaxDynamicSharedMemorySize, SMEM_OUT);

    tab_kernel<<<BB * NN * 32 / 256, 256>>>(pos);
    kv_kernel<<<dim3(SPLITS, HH, BB), 256, SMEM_KV>>>(x, Wk, Wv);
    m_kernel<<<dim3(HH, BB), 256>>>(Wo);
    out_kernel<<<dim3(NN / OCT, BB), 256, SMEM_OUT>>>(x, Wq, out);
}

// round 15
// speedup vs baseline: 2.7353x; 1.8603x over previous
#include <cuda_runtime.h>
#include <math.h>

#define BB 4
#define NN 16384
#define HH 8
#define SPLITS 32
#define KCT 64
#define OCT 128
#define L2_10K 0.4152410118609203f

typedef unsigned long long u64;
typedef unsigned int u32;
typedef unsigned short ush;

__device__ __forceinline__ u64 pk2(float a, float b) {
    u64 r;
    asm("mov.b64 %0, {%1, %2};" : "=l"(r)
        : "r"(__float_as_uint(a)), "r"(__float_as_uint(b)));
    return r;
}
__device__ __forceinline__ float2 up2(u64 a) {
    unsigned int lo, hi;
    asm("mov.b64 {%0, %1}, %2;" : "=r"(lo), "=r"(hi) : "l"(a));
    float2 r; r.x = __uint_as_float(lo); r.y = __uint_as_float(hi);
    return r;
}
__device__ __forceinline__ void fma2(u64& d, u64 a, u64 b) {
    asm("fma.rn.f32x2 %0, %1, %2, %0;" : "+l"(d) : "l"(a), "l"(b));
}
__device__ __forceinline__ u64 mul2(u64 a, u64 b) {
    u64 r; asm("mul.rn.f32x2 %0, %1, %2;" : "=l"(r) : "l"(a), "l"(b)); return r;
}

// bf16 helpers
__device__ __forceinline__ u32 cvt2(float hi, float lo) {
    u32 d; asm("cvt.rn.bf16x2.f32 %0, %1, %2;" : "=r"(d) : "f"(hi), "f"(lo));
    return d;
}
__device__ __forceinline__ float blo(u32 h) { return __uint_as_float(h << 16); }
__device__ __forceinline__ float bhi(u32 h) { return __uint_as_float(h & 0xffff0000u); }
__device__ __forceinline__ void split2(float a, float b, u32& h, u32& l) {
    h = cvt2(b, a);
    l = cvt2(b - bhi(h), a - blo(h));
}
__device__ __forceinline__ u32 smaddr(const void* p) {
    u32 r;
    asm("{ .reg .u64 t; cvta.to.shared.u64 t, %1; cvt.u32.u64 %0, t; }" : "=r"(r) : "l"(p));
    return r;
}
__device__ __forceinline__ void ldsm4(u32* r, u32 a) {
    asm volatile("ldmatrix.sync.aligned.m8n8.x4.shared.b16 {%0,%1,%2,%3}, [%4];"
        : "=r"(r[0]), "=r"(r[1]), "=r"(r[2]), "=r"(r[3]) : "r"(a));
}
__device__ __forceinline__ void ldsm4t(u32* r, u32 a) {
    asm volatile("ldmatrix.sync.aligned.m8n8.x4.trans.shared.b16 {%0,%1,%2,%3}, [%4];"
        : "=r"(r[0]), "=r"(r[1]), "=r"(r[2]), "=r"(r[3]) : "r"(a));
}
__device__ __forceinline__ void hmma(float* c, const u32* a, const u32* b) {
    asm volatile(
        "mma.sync.aligned.m16n8k16.row.col.f32.bf16.bf16.f32 "
        "{%0,%1,%2,%3}, {%4,%5,%6,%7}, {%8,%9}, {%0,%1,%2,%3};"
        : "+f"(c[0]), "+f"(c[1]), "+f"(c[2]), "+f"(c[3])
        : "r"(a[0]), "r"(a[1]), "r"(a[2]), "r"(a[3]), "r"(b[0]), "r"(b[1]));
}

// scratch
__device__ float g_kv_part[BB * HH * SPLITS * 64 * 64];
__device__ u32   g_Mh[BB * HH * 64 * 32];
__device__ u32   g_Ml[BB * HH * 64 * 32];
__device__ float g_tabc[BB * NN * 32];
__device__ float g_tabs[BB * NN * 32];

// ============== tab kernel ==============
__global__ __launch_bounds__(256)
void tab_kernel(const float* __restrict__ pos)
{
    int idx = blockIdx.x * 256 + threadIdx.x;
    float f = pos[idx >> 5] * 64.f * exp2f(-(float)(idx & 31) * L2_10K);
    float s_, c_;
    sincosf(f, &s_, &c_);
    g_tabc[idx] = c_;
    g_tabs[idx] = s_;
}

// ============== kv kernel: bf16 mma, 3-pass split (R12 base, 8 chunks) ==============
// per (b,h,s): 8 chunks of 64 tokens (512 tokens/block).
// smem halves: xk hi/lo [64*72]x2 (x, then k) | v hi/lo [64*72]x2 |
//              W hi [2][64*72] | W lo [2][64*72]  = 36864 halves = 73728 B
__global__ __launch_bounds__(256, 2)
void kv_kernel(const float* __restrict__ x,
               const float* __restrict__ Wk, const float* __restrict__ Wv)
{
    extern __shared__ __align__(16) ush sh[];
    ush* xkh = sh;              // 4608 halves
    ush* xkl = sh + 4608;
    ush* vhs = sh + 9216;
    ush* vls = sh + 13824;
    ush* whb = sh + 18432;      // [sel][64*72]
    ush* wlb = sh + 27648;

    const int tid = threadIdx.x;
    const int b = blockIdx.z, h = blockIdx.y, s = blockIdx.x;
    const int w = tid >> 5, lane = tid & 31;
    const int g = lane >> 2, tc4 = lane & 3;
    const int lr = lane & 15, lc = (lane >> 4) * 8;
    const bool kwarp = (w < 4);
    const int mb = w & 3, rb = mb * 16;
    // GEMM2 tiling: warp owns d-block md (16 rows), cols nhalf*32..+31
    const int md = w & 3, nhalf = w >> 2;

    // stage Wk/Wv split-bf16
    #pragma unroll
    for (int r = 0; r < 16; r++) {
        int p = tid + r * 256;            // [0,4096) pairs
        int sel = p >> 11;
        int q = p & 2047;
        int i = q >> 5, op = (q & 31) * 2;
        const float* Ws = sel ? Wv : Wk;
        float2 wv2 = *(const float2*)&Ws[i * 512 + h * 64 + op];
        u32 hh, ll;
        split2(wv2.x, wv2.y, hh, ll);
        *(u32*)&whb[sel * 4608 + i * 72 + op] = hh;
        *(u32*)&wlb[sel * 4608 + i * 72 + op] = ll;
    }

    const ush* WH = whb + (kwarp ? 0 : 4608);
    const ush* WL = wlb + (kwarp ? 0 : 4608);
    ush* DH = kwarp ? xkh : vhs;
    ush* DL = kwarp ? xkl : vls;

    float kvc[4][4];
    #pragma unroll
    for (int i = 0; i < 4; i++)
        #pragma unroll
        for (int e = 0; e < 4; e++) kvc[i][e] = 0.f;

    const int tpb = NN / SPLITS;          // 512 tokens per block
    #pragma unroll 1
    for (int c = 0; c < tpb / KCT; c++) { // 8 chunks of 64 tokens
        const int tbase = s * tpb + c * KCT;
        __syncthreads();     // prior GEMM2 reads of xk/v done (also covers W staging)

        // stage x split-bf16 (64 tokens)
        const float* xg = x + ((size_t)b * NN + tbase) * 64;
        #pragma unroll
        for (int r = 0; r < 8; r++) {
            int p = tid + r * 256;        // [0,2048) pairs
            int t = p >> 5, ip = (p & 31) * 2;
            float2 v = *(const float2*)&xg[t * 64 + ip];
            u32 hh, ll;
            split2(v.x, v.y, hh, ll);
            *(u32*)&xkh[t * 72 + ip] = hh;
            *(u32*)&xkl[t * 72 + ip] = ll;
        }
        __syncthreads();

        // GEMM1: proj 16 rows x 64 cols per warp (k or v), 3-pass
        float pc[8][4];
        #pragma unroll
        for (int nb = 0; nb < 8; nb++)
            #pragma unroll
            for (int e = 0; e < 4; e++) pc[nb][e] = 0.f;

        #pragma unroll
        for (int kb = 0; kb < 4; kb++) {
            u32 ah[4], al[4];
            ldsm4(ah, smaddr(&xkh[(rb + lr) * 72 + kb * 16 + lc]));
            ldsm4(al, smaddr(&xkl[(rb + lr) * 72 + kb * 16 + lc]));
            #pragma unroll
            for (int nl = 0; nl < 4; nl++) {
                u32 bh[4], bl[4];
                ldsm4t(bh, smaddr(&WH[(kb * 16 + lr) * 72 + nl * 16 + lc]));
                ldsm4t(bl, smaddr(&WL[(kb * 16 + lr) * 72 + nl * 16 + lc]));
                hmma(pc[2 * nl],     ah, &bh[0]);
                hmma(pc[2 * nl],     al, &bh[0]);
                hmma(pc[2 * nl],     ah, &bl[0]);
                hmma(pc[2 * nl + 1], ah, &bh[2]);
                hmma(pc[2 * nl + 1], al, &bh[2]);
                hmma(pc[2 * nl + 1], ah, &bl[2]);
            }
        }
        __syncthreads();     // x reads done before overwrite with k

        // LayerNorm: rows rb+g (elems 0,1) and rb+g+8 (elems 2,3)
        float s1a = 0.f, s2a = 0.f, s1b = 0.f, s2b = 0.f;
        #pragma unroll
        for (int nb = 0; nb < 8; nb++) {
            s1a += pc[nb][0] + pc[nb][1];
            s2a += pc[nb][0] * pc[nb][0] + pc[nb][1] * pc[nb][1];
            s1b += pc[nb][2] + pc[nb][3];
            s2b += pc[nb][2] * pc[nb][2] + pc[nb][3] * pc[nb][3];
        }
        #pragma unroll
        for (int m = 1; m < 4; m <<= 1) {
            s1a += __shfl_xor_sync(0xffffffffu, s1a, m);
            s2a += __shfl_xor_sync(0xffffffffu, s2a, m);
            s1b += __shfl_xor_sync(0xffffffffu, s1b, m);
            s2b += __shfl_xor_sync(0xffffffffu, s2b, m);
        }
        float ma = s1a * (1.f / 64.f);
        float ra = rsqrtf(fmaxf(s2a * (1.f / 64.f) - ma * ma, 0.f) + 1e-5f);
        float mb_ = s1b * (1.f / 64.f);
        float rbn = rsqrtf(fmaxf(s2b * (1.f / 64.f) - mb_ * mb_, 0.f) + 1e-5f);
        #pragma unroll
        for (int nb = 0; nb < 8; nb++) {
            pc[nb][0] = (pc[nb][0] - ma) * ra;
            pc[nb][1] = (pc[nb][1] - ma) * ra;
            pc[nb][2] = (pc[nb][2] - mb_) * rbn;
            pc[nb][3] = (pc[nb][3] - mb_) * rbn;
        }

        if (kwarp) {   // RoPE on k: col c <-> c+32 == nb <-> nb+4
            const size_t tr = (size_t)b * NN + tbase + rb + g;
            const float* tcb = &g_tabc[tr * 32 + 2 * tc4];
            const float* tsb = &g_tabs[tr * 32 + 2 * tc4];
            #pragma unroll
            for (int nb = 0; nb < 4; nb++) {
                float2 c0 = *(const float2*)(tcb + 8 * nb);
                float2 c1 = *(const float2*)(tcb + 256 + 8 * nb);
                float2 s0 = *(const float2*)(tsb + 8 * nb);
                float2 s1 = *(const float2*)(tsb + 256 + 8 * nb);
                float cs[4] = { c0.x, c0.y, c1.x, c1.y };
                float sn[4] = { s0.x, s0.y, s1.x, s1.y };
                #pragma unroll
                for (int e = 0; e < 4; e++) {
                    float lo = pc[nb][e], hi = pc[nb + 4][e];
                    pc[nb][e]     = lo * cs[e] - hi * sn[e];
                    pc[nb + 4][e] = hi * cs[e] + lo * sn[e];
                }
            }
        }

        // store split-bf16 k/v
        #pragma unroll
        for (int nb = 0; nb < 8; nb++) {
            u32 hh, ll;
            split2(pc[nb][0], pc[nb][1], hh, ll);
            *(u32*)&DH[(rb + g) * 72 + 8 * nb + 2 * tc4] = hh;
            *(u32*)&DL[(rb + g) * 72 + 8 * nb + 2 * tc4] = ll;
            split2(pc[nb][2], pc[nb][3], hh, ll);
            *(u32*)&DH[(rb + g + 8) * 72 + 8 * nb + 2 * tc4] = hh;
            *(u32*)&DL[(rb + g + 8) * 72 + 8 * nb + 2 * tc4] = ll;
        }
        __syncthreads();

        // GEMM2: kv[d][e] += k^T v  (A via trans from [t][d]: perm {0,2,1,3})
        #pragma unroll
        for (int kt = 0; kt < 4; kt++) {
            u32 t0[4], t1[4];
            ldsm4t(t0, smaddr(&xkh[(kt * 16 + lr) * 72 + md * 16 + lc]));
            ldsm4t(t1, smaddr(&xkl[(kt * 16 + lr) * 72 + md * 16 + lc]));
            u32 ah[4] = { t0[0], t0[2], t0[1], t0[3] };
            u32 al[4] = { t1[0], t1[2], t1[1], t1[3] };
            #pragma unroll
            for (int nl = 0; nl < 2; nl++) {
                u32 bh[4], bl[4];
                ldsm4t(bh, smaddr(&vhs[(kt * 16 + lr) * 72 + nhalf * 32 + nl * 16 + lc]));
                ldsm4t(bl, smaddr(&vls[(kt * 16 + lr) * 72 + nhalf * 32 + nl * 16 + lc]));
                hmma(kvc[2 * nl],     ah, &bh[0]);
                hmma(kvc[2 * nl],     al, &bh[0]);
                hmma(kvc[2 * nl],     ah, &bl[0]);
                hmma(kvc[2 * nl + 1], ah, &bh[2]);
                hmma(kvc[2 * nl + 1], al, &bh[2]);
                hmma(kvc[2 * nl + 1], ah, &bl[2]);
            }
        }
    }

    // epilogue: fp32 partial kv
    float* dst = g_kv_part + ((size_t)((b * HH + h) * SPLITS + s)) * 4096;
    const int d0 = md * 16 + g;
    #pragma unroll
    for (int nb = 0; nb < 4; nb++) {
        int col = nhalf * 32 + 8 * nb + 2 * tc4;
        float2 v0 = { kvc[nb][0], kvc[nb][1] };
        float2 v1 = { kvc[nb][2], kvc[nb][3] };
        *(float2*)&dst[d0 * 64 + col]       = v0;
        *(float2*)&dst[(d0 + 8) * 64 + col] = v1;
    }
}

// ============== m kernel: reduce + M=(kv@Wo)/N, emit bf16 hi/lo ==============
__global__ __launch_bounds__(256, 1)
void m_kernel(const float* __restrict__ Wo)
{
    __shared__ float kvs[64 * 66];
    __shared__ float wo[64 * 64];
    const int tid = threadIdx.x;
    const int h = blockIdx.x, b = blockIdx.y;
    const float* src = g_kv_part + (size_t)(b * HH + h) * SPLITS * 4096;

    #pragma unroll
    for (int r = 0; r < 16; r++) {
        int idx = tid + r * 256;
        float acc = 0.f;
        #pragma unroll 4
        for (int s = 0; s < SPLITS; s++) acc += src[s * 4096 + idx];
        int i = idx >> 6, j = idx & 63;
        kvs[i * 66 + j] = acc;
        wo[idx] = Wo[(h * 64 + i) * 64 + j];
    }
    __syncthreads();

    const int i0 = (tid >> 3) * 2;
    const int d0 = (tid & 7) * 8;
    u64 a[2][4];
    #pragma unroll
    for (int ij = 0; ij < 2; ij++)
        #pragma unroll
        for (int p = 0; p < 4; p++) a[ij][p] = 0ull;

    #pragma unroll 8
    for (int j = 0; j < 64; j++) {
        float k0 = kvs[i0 * 66 + j], k1 = kvs[(i0 + 1) * 66 + j];
        u64 p0 = pk2(k0, k0), p1 = pk2(k1, k1);
        ulonglong2 w0 = *(const ulonglong2*)&wo[j * 64 + d0];
        ulonglong2 w1 = *(const ulonglong2*)&wo[j * 64 + d0 + 4];
        u64 wp[4] = { w0.x, w0.y, w1.x, w1.y };
        #pragma unroll
        for (int p = 0; p < 4; p++) {
            fma2(a[0][p], p0, wp[p]);
            fma2(a[1][p], p1, wp[p]);
        }
    }
    const float sc = 1.f / (float)NN;
    const u64 sc2 = pk2(sc, sc);
    const int mbase = (b * HH + h) * 64 * 32;
    #pragma unroll
    for (int ij = 0; ij < 2; ij++)
        #pragma unroll
        for (int p = 0; p < 4; p++) {
            float2 v = up2(mul2(a[ij][p], sc2));
            u32 hh, ll;
            split2(v.x, v.y, hh, ll);
            int idx = mbase + (i0 + ij) * 32 + (d0 >> 1) + p;
            g_Mh[idx] = hh;
            g_Ml[idx] = ll;
        }
}

// ============== out kernel (frozen from R9): bf16 mma, 3-pass ==============
__global__ __launch_bounds__(256, 2)
void out_kernel(const float* __restrict__ x,
                const float* __restrict__ Wq, float* __restrict__ out)
{
    extern __shared__ __align__(16) ush sh[];
    ush* xbh = sh;
    ush* xbl = xbh + 128 * 72;
    ush* whs = xbl + 128 * 72;
    ush* wls = whs + 64 * 72;
    ush* mhs = wls + 64 * 72;
    ush* mls = mhs + 64 * 72;

    const int tid = threadIdx.x;
    const int b = blockIdx.y;
    const int tbase = blockIdx.x * OCT;
    const int w = tid >> 5, lane = tid & 31;
    const int g = lane >> 2, tc4 = lane & 3;
    const int rb = w * 16;
    const int lr = lane & 15, lc = (lane >> 4) * 8;

    const float* xg = x + ((size_t)b * NN + tbase) * 64;
    #pragma unroll
    for (int r = 0; r < 16; r++) {
        int p = tid + r * 256;
        int t = p >> 5, ip = (p & 31) * 2;
        float2 v = *(const float2*)&xg[t * 64 + ip];
        u32 hh, ll;
        split2(v.x, v.y, hh, ll);
        *(u32*)&xbh[t * 72 + ip] = hh;
        *(u32*)&xbl[t * 72 + ip] = ll;
    }

    float oc[8][4];
    #pragma unroll
    for (int nb = 0; nb < 8; nb++)
        #pragma unroll
        for (int e = 0; e < 4; e++) oc[nb][e] = 0.f;

    const size_t trow = (size_t)b * NN + tbase + rb + g;
    const float* tcb = &g_tabc[trow * 32 + 2 * tc4];
    const float* tsb = &g_tabs[trow * 32 + 2 * tc4];

    #pragma unroll 1
    for (int hh8 = 0; hh8 < HH; hh8++) {
        const int mbase = (b * HH + hh8) * 64 * 32;
        #pragma unroll
        for (int r = 0; r < 8; r++) {
            int p = tid + r * 256;
            int i = p >> 5, op = (p & 31) * 2;
            float2 wv = *(const float2*)&Wq[i * 512 + hh8 * 64 + op];
            u32 whv, wlv;
            split2(wv.x, wv.y, whv, wlv);
            *(u32*)&whs[i * 72 + op] = whv;
            *(u32*)&wls[i * 72 + op] = wlv;
            *(u32*)&mhs[i * 72 + op] = g_Mh[mbase + i * 32 + (op >> 1)];
            *(u32*)&mls[i * 72 + op] = g_Ml[mbase + i * 32 + (op >> 1)];
        }
        __syncthreads();

        float qc[8][4];
        #pragma unroll
        for (int nb = 0; nb < 8; nb++)
            #pragma unroll
            for (int e = 0; e < 4; e++) qc[nb][e] = 0.f;

        #pragma unroll
        for (int kb = 0; kb < 4; kb++) {
            u32 ah[4], al[4];
            ldsm4(ah, smaddr(&xbh[(rb + lr) * 72 + kb * 16 + lc]));
            ldsm4(al, smaddr(&xbl[(rb + lr) * 72 + kb * 16 + lc]));
            #pragma unroll
            for (int nb2 = 0; nb2 < 4; nb2++) {
                u32 bh[4], bl[4];
                ldsm4t(bh, smaddr(&whs[(kb * 16 + lr) * 72 + nb2 * 16 + lc]));
                ldsm4t(bl, smaddr(&wls[(kb * 16 + lr) * 72 + nb2 * 16 + lc]));
                hmma(qc[2 * nb2],     ah, &bh[0]);
                hmma(qc[2 * nb2],     al, &bh[0]);
                hmma(qc[2 * nb2],     ah, &bl[0]);
                hmma(qc[2 * nb2 + 1], ah, &bh[2]);
                hmma(qc[2 * nb2 + 1], al, &bh[2]);
                hmma(qc[2 * nb2 + 1], ah, &bl[2]);
            }
        }

        #pragma unroll
        for (int nb = 0; nb < 4; nb++) {
            float2 c0 = *(const float2*)(tcb + 8 * nb);
            float2 c1 = *(const float2*)(tcb + 256 + 8 * nb);
            float2 s0 = *(const float2*)(tsb + 8 * nb);
            float2 s1 = *(const float2*)(tsb + 256 + 8 * nb);
            float cs[4] = { c0.x, c0.y, c1.x, c1.y };
            float sn[4] = { s0.x, s0.y, s1.x, s1.y };
            #pragma unroll
            for (int e = 0; e < 4; e++) {
                float lo = qc[nb][e], hi = qc[nb + 4][e];
                qc[nb][e]     = lo * cs[e] - hi * sn[e];
                qc[nb + 4][e] = hi * cs[e] + lo * sn[e];
            }
        }

        #pragma unroll
        for (int kb = 0; kb < 4; kb++) {
            u32 qah[4], qal[4];
            split2(qc[2 * kb][0],     qc[2 * kb][1],     qah[0], qal[0]);
            split2(qc[2 * kb][2],     qc[2 * kb][3],     qah[1], qal[1]);
            split2(qc[2 * kb + 1][0], qc[2 * kb + 1][1], qah[2], qal[2]);
            split2(qc[2 * kb + 1][2], qc[2 * kb + 1][3], qah[3], qal[3]);
            #pragma unroll
            for (int nb2 = 0; nb2 < 4; nb2++) {
                u32 bh[4], bl[4];
                ldsm4t(bh, smaddr(&mhs[(kb * 16 + lr) * 72 + nb2 * 16 + lc]));
                ldsm4t(bl, smaddr(&mls[(kb * 16 + lr) * 72 + nb2 * 16 + lc]));
                hmma(oc[2 * nb2],     qah, &bh[0]);
                hmma(oc[2 * nb2],     qal, &bh[0]);
                hmma(oc[2 * nb2],     qah, &bl[0]);
                hmma(oc[2 * nb2 + 1], qah, &bh[2]);
                hmma(oc[2 * nb2 + 1], qal, &bh[2]);
                hmma(oc[2 * nb2 + 1], qah, &bl[2]);
            }
        }
        __syncthreads();
    }

    float* outg = out + ((size_t)b * NN + tbase + rb) * 64;
    #pragma unroll
    for (int nb = 0; nb < 8; nb++) {
        float2 v0 = { oc[nb][0], oc[nb][1] };
        float2 v1 = { oc[nb][2], oc[nb][3] };
        *(float2*)&outg[g * 64 + 8 * nb + 2 * tc4]       = v0;
        *(float2*)&outg[(g + 8) * 64 + 8 * nb + 2 * tc4] = v1;
    }
}

// =====================================================================
extern "C" void kernel_launch(void* const* d_in, const int* in_sizes, int n_in,
                              void* d_out, int out_size)
{
    const float* x   = (const float*)d_in[0];
    const float* pos = (const float*)d_in[1];
    const float* Wq  = (const float*)d_in[2];
    const float* Wk  = (const float*)d_in[3];
    const float* Wv  = (const float*)d_in[4];
    const float* Wo  = (const float*)d_in[5];
    float* out = (float*)d_out;

    const int SMEM_KV  = 36864 * 2;                         // 73728 B
    const int SMEM_OUT = (2 * 128 * 72 + 4 * 64 * 72) * 2;  // 73728 B
    cudaFuncSetAttribute(kv_kernel,  cudaFuncAttributeMaxDynamicSharedMemorySize, SMEM_KV);
    cudaFuncSetAttribute(out_kernel, cudaFuncAttributeMaxDynamicSharedMemorySize, SMEM_OUT);

    tab_kernel<<<BB * NN * 32 / 256, 256>>>(pos);
    kv_kernel<<<dim3(SPLITS, HH, BB), 256, SMEM_KV>>>(x, Wk, Wv);
    m_kernel<<<dim3(HH, BB), 256>>>(Wo);
    out_kernel<<<dim3(NN / OCT, BB), 256, SMEM_OUT>>>(x, Wq, out);
}